// round 12
// baseline (speedup 1.0000x reference)
#include <cuda_runtime.h>
#include <math.h>
#include <stdint.h>

#define NB 8
#define NC 128
#define NH 128
#define NW 128
#define NL (NH*NW)          // 16384
#define NMID 32
#define KTOT 416
#define NPAN 13
#define NFROWS 288          // nsum(128) + diff(128) + silu(32)
#define NROWBLK 1024
#define NTOT (NB*NC*NL)
#define VT 2048             // vred tile positions

// ---------------- device scratch ----------------
__device__ __align__(16) float g_Fg[(size_t)NB*NFROWS*NL];
__device__ float g_gap[NB][NC];
__device__ __align__(16) float g_Bt[KTOT*NC];
__device__ float g_ck[NB][3][NC];
__device__ float g_u[NB][NMID];
__device__ float g_b2p[NC];
__device__ float g_psum[NC*NROWBLK];
__device__ float g_psq[NC*NROWBLK];
__device__ float g_scale[NC];
__device__ float g_shift[NC];

// ---------------- helpers ----------------
__device__ __forceinline__ float to_tf32(float x) {
    uint32_t o;
    asm("cvt.rna.tf32.f32 %0, %1;" : "=r"(o) : "f"(x));
    return __uint_as_float(o);
}
__device__ __forceinline__ uint32_t cvt_rna_u(uint32_t x) {
    uint32_t o;
    asm("cvt.rna.tf32.f32 %0, %1;" : "=r"(o) : "f"(__uint_as_float(x)));
    return o;
}
__device__ __forceinline__ void mma_tf32(float* d, const uint32_t* a, const uint32_t* b) {
    asm volatile("mma.sync.aligned.m16n8k8.row.col.f32.tf32.tf32.f32 "
        "{%0,%1,%2,%3}, {%4,%5,%6,%7}, {%8,%9}, {%0,%1,%2,%3};"
        : "+f"(d[0]), "+f"(d[1]), "+f"(d[2]), "+f"(d[3])
        : "r"(a[0]), "r"(a[1]), "r"(a[2]), "r"(a[3]), "r"(b[0]), "r"(b[1]));
}
__device__ __forceinline__ uint32_t smem_u32(const void* p) {
    uint32_t a;
    asm("{ .reg .u64 t; cvta.to.shared.u64 t, %1; cvt.u32.u64 %0, t; }" : "=r"(a) : "l"(p));
    return a;
}
__device__ __forceinline__ void cp16(uint32_t d, const void* s, bool pred) {
    int sz = pred ? 16 : 0;
    asm volatile("cp.async.cg.shared.global [%0], [%1], 16, %2;"
                 :: "r"(d), "l"(s), "r"(sz) : "memory");
}
__device__ __forceinline__ void cp_commit() {
    asm volatile("cp.async.commit_group;" ::: "memory");
}
#define CP_WAIT(n) asm volatile("cp.async.wait_group %0;" :: "n"(n) : "memory")

// ---------------- fold weights — 512 threads, 4-way K split ----------------
__global__ __launch_bounds__(512) void k_prepw(
        const float* __restrict__ wp,  const float* __restrict__ wout,
        const float* __restrict__ wdw, const float* __restrict__ win,
        const float* __restrict__ w2,  const float* __restrict__ b2,
        const float* __restrict__ dwp) {
    const int o = blockIdx.x, tid = threadIdx.x;
    const int c = tid & 127, part = tid >> 7;
    __shared__ float wps[NC], q[NC];
    __shared__ float par[4][NC], parb[4][NC];
    if (tid < NC) wps[tid] = wp[o*NC + tid];
    __syncthreads();
    {
        float a = 0.f;
        const int t0 = part * 32;
        #pragma unroll 8
        for (int j = 0; j < 32; j++) a = fmaf(wps[t0+j], wout[(t0+j)*NC + c], a);
        par[part][c] = a;
    }
    __syncthreads();
    if (tid < NC) q[tid] = (par[0][tid] + par[1][tid]) + (par[2][tid] + par[3][tid]);
    __syncthreads();
    {
        const int t0 = part * 32;
        float a1 = 0.f, a2 = 0.f;
        #pragma unroll 8
        for (int j = 0; j < 32; j++) {
            int s = t0 + j;
            float qs = q[s];
            float w1v = wdw[s*3 + 1], w02 = wdw[s*3 + 0] + wdw[s*3 + 2];
            float wi = win[s*NC + c];
            a1 = fmaf(qs * w1v, wi, a1);
            a2 = fmaf(qs * w02, wi, a2);
        }
        par[part][c] = a1; parb[part][c] = a2;
    }
    __syncthreads();
    if (tid < NC) {
        float A1 = (par[0][tid] + par[1][tid]) + (par[2][tid] + par[3][tid]) + wps[tid];
        float A2 = 0.25f * ((parb[0][tid] + parb[1][tid]) + (parb[2][tid] + parb[3][tid]));
        g_Bt[tid*NC + o]          = to_tf32(A1);
        g_Bt[(NC + tid)*NC + o]   = to_tf32(A2);
        g_Bt[(2*NC + tid)*NC + o] = to_tf32(dwp[0] * wps[tid]);
    }
    __syncthreads();
    if (tid < NC) {
        int m = tid & 31, p4 = tid >> 5;
        float s4 = 0.f;
        const int t0 = p4 * 32;
        #pragma unroll 8
        for (int j = 0; j < 32; j++) s4 = fmaf(wps[t0+j], w2[(t0+j)*NMID + m], s4);
        par[p4][m] = s4;
        parb[0][tid] = wps[tid] * b2[tid];
    }
    __syncthreads();
    if (tid < 32) {
        g_Bt[(3*NC + tid)*NC + o] =
            to_tf32((par[0][tid] + par[1][tid]) + (par[2][tid] + par[3][tid]));
        float s = (parb[0][tid] + parb[0][tid+32]) + (parb[0][tid+64] + parb[0][tid+96]);
        for (int ofs = 16; ofs; ofs >>= 1) s += __shfl_xor_sync(0xffffffff, s, ofs);
        if (tid == 0) g_b2p[o] = s;
    }
}

// ---------------- per-batch vectors — 1024 threads, 8-way K split ----------------
__global__ __launch_bounds__(1024) void k_prep3(
        const float* __restrict__ wci, const float* __restrict__ wdwch,
        const float* __restrict__ wco, const float* __restrict__ w1) {
    const int b = blockIdx.x, tid = threadIdx.x;
    const int c = tid & 127, part = tid >> 7;
    __shared__ float gs[NC], g2s[NC];
    __shared__ float par[8][NC];
    __shared__ float par3[3][8][NC];
    __shared__ float nrm_s;
    if (tid < NC) { float g = g_gap[b][tid]; par[0][tid] = g * g; }
    __syncthreads();
    if (tid < 32) {
        float s = (par[0][tid] + par[0][tid+32]) + (par[0][tid+64] + par[0][tid+96]);
        for (int o = 16; o; o >>= 1) s += __shfl_xor_sync(0xffffffff, s, o);
        if (tid == 0) nrm_s = fmaxf(sqrtf(s), 1e-12f);
    }
    __syncthreads();
    if (tid < NC) gs[tid] = g_gap[b][tid] / nrm_s;
    __syncthreads();
    {
        float a = 0.f;
        const int t0 = part * 16;
        #pragma unroll
        for (int j = 0; j < 16; j++) a = fmaf(gs[t0+j], wco[(t0+j)*NC + c], a);
        par[part][c] = a;
    }
    __syncthreads();
    if (tid < NC) {
        float a = 0.f;
        #pragma unroll
        for (int p = 0; p < 8; p++) a += par[p][tid];
        g2s[tid] = a;
    }
    __syncthreads();
    {
        const int t0 = part * 16;
        float s0 = 0.f, s1 = 0.f, s2 = 0.f;
        #pragma unroll
        for (int j = 0; j < 16; j++) {
            int t = t0 + j;
            float wv = wci[t*NC + c] * g2s[t];
            s0 = fmaf(wv, wdwch[t*3 + 0], s0);
            s1 = fmaf(wv, wdwch[t*3 + 1], s1);
            s2 = fmaf(wv, wdwch[t*3 + 2], s2);
        }
        par3[0][part][c] = s0; par3[1][part][c] = s1; par3[2][part][c] = s2;
    }
    __syncthreads();
    if (tid < 384) {
        int k = tid >> 7, cc = tid & 127;
        float a = 0.f;
        #pragma unroll
        for (int p = 0; p < 8; p++) a += par3[k][p][cc];
        g_ck[b][k][cc] = a;
    }
    {
        int m = tid & 31, pt = tid >> 5;
        const int t0 = pt * 4;
        float s = 0.f;
        #pragma unroll
        for (int j = 0; j < 4; j++) s = fmaf(w1[m*NC + t0+j], gs[t0+j], s);
        ((float*)par)[pt*32 + m] = s;
    }
    __syncthreads();
    if (tid < NMID) {
        float s = 0.f;
        #pragma unroll
        for (int p = 0; p < 32; p++) s += ((float*)par)[p*32 + tid];
        g_u[b][tid] = s;
    }
}

// ---------------- stencil build + fused gap: 512 threads, one (b,c) plane ----------------
__global__ __launch_bounds__(512) void k_build(const float* __restrict__ x) {
    __shared__ float red[512];
    const int bx = blockIdx.x;
    const int b = bx >> 7, c = bx & 127;
    const float* xp = x + (size_t)(b*NC + c) * NL;
    float* nrow = g_Fg + (size_t)b*NFROWS*NL + (size_t)c*NL;
    float* drow = nrow + (size_t)NC*NL;
    const int tid = threadIdx.x;
    float gsum = 0.f;
    #pragma unroll 2
    for (int r = 0; r < 8; r++) {
        int p4 = tid + (r << 9);
        int pos = p4 << 2;
        int i = pos >> 7, j0 = pos & 127;
        float4 c4 = ((const float4*)xp)[p4];
        gsum += (c4.x + c4.y) + (c4.z + c4.w);
        float lprev = (pos > 0) ? xp[pos-1] : 0.f;
        float rnext = (pos < NL-4) ? xp[pos+4] : 0.f;
        float u0,u1,u2,u3, d0,d1,d2,d3;
        if (i > 0) {
            float4 up4 = ((const float4*)xp)[p4-32];
            u0 = up4.x; u1 = up4.y; u2 = up4.z; u3 = up4.w;
        } else {
            u0 = (j0 > 0) ? xp[127*NW + j0-1] : 0.f;
            u1 = xp[127*NW + j0];
            u2 = xp[127*NW + j0+1];
            u3 = xp[127*NW + j0+2];
        }
        if (i < 127) {
            float4 dn4 = ((const float4*)xp)[p4+32];
            d0 = dn4.x; d1 = dn4.y; d2 = dn4.z; d3 = dn4.w;
        } else {
            d0 = xp[j0+1]; d1 = xp[j0+2]; d2 = xp[j0+3];
            d3 = (j0+3 < 127) ? xp[j0+4] : 0.f;
        }
        float l0 = lprev, l1 = c4.x, l2 = c4.y, l3 = c4.z;
        float r0 = c4.y, r1 = c4.z, r2 = c4.w, r3 = rnext;
        ((float4*)nrow)[p4] = make_float4(to_tf32((l0+r0)+(u0+d0)), to_tf32((l1+r1)+(u1+d1)),
                                          to_tf32((l2+r2)+(u2+d2)), to_tf32((l3+r3)+(u3+d3)));
        float lr0 = (j0 == 0) ? c4.y : lprev;
        float rr3 = (j0 == 124) ? c4.z : rnext;
        float ur0,ur1,ur2,ur3, dr0,dr1,dr2,dr3;
        if (i > 0) { ur0=u0; ur1=u1; ur2=u2; ur3=u3; }
        else       { ur0=d0; ur1=d1; ur2=d2; ur3=d3; }
        if (i < 127) { dr0=d0; dr1=d1; dr2=d2; dr3=d3; }
        else         { dr0=u0; dr1=u1; dr2=u2; dr3=u3; }
        float df0 = 0.25f*((fabsf(c4.x-lr0)+fabsf(c4.x-c4.y))+(fabsf(c4.x-ur0)+fabsf(c4.x-dr0)));
        float df1 = 0.25f*((fabsf(c4.y-c4.x)+fabsf(c4.y-c4.z))+(fabsf(c4.y-ur1)+fabsf(c4.y-dr1)));
        float df2 = 0.25f*((fabsf(c4.z-c4.y)+fabsf(c4.z-c4.w))+(fabsf(c4.z-ur2)+fabsf(c4.z-dr2)));
        float df3 = 0.25f*((fabsf(c4.w-c4.z)+fabsf(c4.w-rr3))+(fabsf(c4.w-ur3)+fabsf(c4.w-dr3)));
        ((float4*)drow)[p4] = make_float4(to_tf32(df0), to_tf32(df1), to_tf32(df2), to_tf32(df3));
    }
    red[tid] = gsum;
    __syncthreads();
    for (int k = 256; k > 0; k >>= 1) {
        if (tid < k) red[tid] += red[tid + k];
        __syncthreads();
    }
    if (tid == 0) g_gap[b][c] = red[0] * (1.0f / NL);
}

// ---------------- v reduction + silu rows: vectorized 3-row GEMV ----------------
// grid = NB*8 blocks of VT=2048 positions; 512 threads, 1 float4 (4 pos) each
__global__ __launch_bounds__(512) void k_vred(const float* __restrict__ x,
                                              const float* __restrict__ b1) {
    __shared__ float s0[VT + 1], s2[VT + 1];
    __shared__ float cks[3*NC], us[NMID], b1s[NMID];
    const int tid = threadIdx.x;
    const int b = blockIdx.x >> 3;
    const int tb = (blockIdx.x & 7) << 11;
    const float* xb = x + (size_t)b * NC * NL;

    for (int q = tid; q < 3*NC; q += 512) cks[q] = (&g_ck[b][0][0])[q];
    if (tid < NMID) { us[tid] = g_u[b][tid]; b1s[tid] = b1[tid]; }
    __syncthreads();

    float a0x=0,a0y=0,a0z=0,a0w=0, a1x=0,a1y=0,a1z=0,a1w=0, a2x=0,a2y=0,a2z=0,a2w=0;
    const float4* px = (const float4*)(xb + tb) + tid;
    const bool hL = (tid == 0) && (tb > 0);
    const bool hR = (tid == 511) && (tb + VT < NL);
    float h = 0.f;
    #pragma unroll 4
    for (int c = 0; c < NC; c++) {
        float4 xv = px[c * (NL/4)];
        float c0 = cks[c], c1 = cks[NC + c], c2 = cks[2*NC + c];
        a0x = fmaf(c0, xv.x, a0x); a0y = fmaf(c0, xv.y, a0y);
        a0z = fmaf(c0, xv.z, a0z); a0w = fmaf(c0, xv.w, a0w);
        a1x = fmaf(c1, xv.x, a1x); a1y = fmaf(c1, xv.y, a1y);
        a1z = fmaf(c1, xv.z, a1z); a1w = fmaf(c1, xv.w, a1w);
        a2x = fmaf(c2, xv.x, a2x); a2y = fmaf(c2, xv.y, a2y);
        a2z = fmaf(c2, xv.z, a2z); a2w = fmaf(c2, xv.w, a2w);
        if (hL) h = fmaf(c0, xb[(size_t)c*NL + tb - 1], h);
        if (hR) h = fmaf(c2, xb[(size_t)c*NL + tb + VT], h);
    }
    const int i0 = tid << 2;
    s0[i0+1] = a0x; s0[i0+2] = a0y; s0[i0+3] = a0z; s0[i0+4] = a0w;
    s2[i0]   = a2x; s2[i0+1] = a2y; s2[i0+2] = a2z; s2[i0+3] = a2w;
    if (tid == 0)   s0[0]  = hL ? h : 0.f;
    if (tid == 511) s2[VT] = hR ? h : 0.f;
    __syncthreads();
    float v0 = s0[i0]   + a1x + s2[i0+1];
    float v1 = s0[i0+1] + a1y + s2[i0+2];
    float v2 = s0[i0+2] + a1z + s2[i0+3];
    float v3 = s0[i0+3] + a1w + s2[i0+4];

    float* dst = g_Fg + (size_t)b*NFROWS*NL + (size_t)(2*NC)*NL + tb + i0;
    #pragma unroll 4
    for (int m = 0; m < NMID; m++) {
        float um = us[m], bm = b1s[m];
        float z0 = fmaf(um, v0, bm), z1 = fmaf(um, v1, bm);
        float z2 = fmaf(um, v2, bm), z3 = fmaf(um, v3, bm);
        *(float4*)(dst + (size_t)m * NL) = make_float4(
            to_tf32(z0 / (1.f + __expf(-z0))), to_tf32(z1 / (1.f + __expf(-z1))),
            to_tf32(z2 / (1.f + __expf(-z2))), to_tf32(z3 / (1.f + __expf(-z3))));
    }
}

// ---------------- streaming GEMM (R8 known-good), writes pre-BN to out ----------------
#define GSMEM (3*8192*4)

__global__ __launch_bounds__(256, 2) void k_gemm(const float* __restrict__ x,
                                                 float* __restrict__ out) {
    extern __shared__ __align__(16) float sm[];
    const int tid = threadIdx.x;
    const int b = blockIdx.x >> 7;
    const int posb = (blockIdx.x & 127) << 7;
    const float* xb  = x + (size_t)b * NC * NL + posb;
    const float* fgb = g_Fg + (size_t)b * NFROWS * NL + posb;

    auto issueP = [&](int p, int st) {
        int k0 = p * 32;
        const float* bsrc = (k0 < NC) ? (xb + (size_t)k0 * NL) : (fgb + (size_t)(k0 - NC) * NL);
        const float* asrc = g_Bt + k0 * NC;
        uint32_t ab = smem_u32(sm + st * 8192);
        uint32_t bb = ab + 16384;
        #pragma unroll
        for (int r = 0; r < 4; r++) {
            int f = tid + (r << 8);
            int kr = f >> 5, j4 = f & 31;
            int sw = (kr*32 + (j4 ^ ((kr & 3) << 1))) * 16;
            cp16(ab + sw, asrc + kr*NC + (j4 << 2), true);
            cp16(bb + sw, bsrc + (size_t)kr*NL + (j4 << 2), true);
        }
        cp_commit();
    };
    issueP(0, 0); issueP(1, 1);

    const int lane = tid & 31, g = lane >> 2, tg = lane & 3;
    const int w = tid >> 5, mbase = (w >> 2) * 64, nbase = (w & 3) * 32;
    const int swa = tg << 3;
    float dacc[4][4][4];
    #pragma unroll
    for (int mt = 0; mt < 4; mt++)
        #pragma unroll
        for (int nt = 0; nt < 4; nt++)
            #pragma unroll
            for (int qq = 0; qq < 4; qq++) dacc[mt][nt][qq] = 0.f;

    auto mmaPanel = [&](const uint32_t* As, bool cvt) {
        const uint32_t* Fu = As + 4096;
        #pragma unroll
        for (int ks = 0; ks < 4; ks++) {
            const int kr = ks * 8;
            uint32_t af[4][4], bf[4][2];
            #pragma unroll
            for (int nt = 0; nt < 4; nt++) {
                int n = nbase + nt*8 + g;
                uint32_t v0 = Fu[(kr + tg)*128 + (n ^ swa)];
                uint32_t v1 = Fu[(kr + tg + 4)*128 + (n ^ swa)];
                bf[nt][0] = cvt ? cvt_rna_u(v0) : v0;
                bf[nt][1] = cvt ? cvt_rna_u(v1) : v1;
            }
            #pragma unroll
            for (int mt = 0; mt < 4; mt++) {
                int o = mbase + mt*16 + g;
                af[mt][0] = As[(kr + tg)*128 + (o ^ swa)];
                af[mt][1] = As[(kr + tg)*128 + ((o+8) ^ swa)];
                af[mt][2] = As[(kr + tg + 4)*128 + (o ^ swa)];
                af[mt][3] = As[(kr + tg + 4)*128 + ((o+8) ^ swa)];
            }
            #pragma unroll
            for (int mt = 0; mt < 4; mt++)
                #pragma unroll
                for (int nt = 0; nt < 4; nt++)
                    mma_tf32(dacc[mt][nt], af[mt], bf[nt]);
        }
    };

    int st = 0;
    #pragma unroll 1
    for (int p = 0; p < NPAN; p++) {
        if (p < NPAN-1) { CP_WAIT(1); } else { CP_WAIT(0); }
        __syncthreads();
        if (p + 2 < NPAN) issueP(p + 2, (p + 2) % 3);
        mmaPanel((const uint32_t*)(sm + st * 8192), p < 4);
        st = (st == 2) ? 0 : st + 1;
    }
    __syncthreads();

    // ---- epilogue: bias, pre-BN store to out, BN partials ----
    float* sred = sm;
    #pragma unroll
    for (int mt = 0; mt < 4; mt++) {
        int o0 = mbase + mt*16 + g, o1 = o0 + 8;
        float bb0 = g_b2p[o0], bb1 = g_b2p[o1];
        float* row0 = &out[(size_t)(b*NC + o0) * NL + posb];
        float* row1 = &out[(size_t)(b*NC + o1) * NL + posb];
        float s0 = 0.f, q0 = 0.f, s1 = 0.f, q1 = 0.f;
        #pragma unroll
        for (int nt = 0; nt < 4; nt++) {
            float v0 = dacc[mt][nt][0] + bb0, v1 = dacc[mt][nt][1] + bb0;
            float v2 = dacc[mt][nt][2] + bb1, v3 = dacc[mt][nt][3] + bb1;
            int j = nbase + nt*8 + 2*tg;
            *(float2*)(row0 + j) = make_float2(v0, v1);
            *(float2*)(row1 + j) = make_float2(v2, v3);
            s0 += v0 + v1; q0 = fmaf(v0, v0, q0); q0 = fmaf(v1, v1, q0);
            s1 += v2 + v3; q1 = fmaf(v2, v2, q1); q1 = fmaf(v3, v3, q1);
        }
        s0 += __shfl_xor_sync(0xffffffff, s0, 1); s0 += __shfl_xor_sync(0xffffffff, s0, 2);
        q0 += __shfl_xor_sync(0xffffffff, q0, 1); q0 += __shfl_xor_sync(0xffffffff, q0, 2);
        s1 += __shfl_xor_sync(0xffffffff, s1, 1); s1 += __shfl_xor_sync(0xffffffff, s1, 2);
        q1 += __shfl_xor_sync(0xffffffff, q1, 1); q1 += __shfl_xor_sync(0xffffffff, q1, 2);
        if (tg == 0) {
            int nwq = w & 3;
            sred[o0*4 + nwq] = s0; sred[512 + o0*4 + nwq] = q0;
            sred[o1*4 + nwq] = s1; sred[512 + o1*4 + nwq] = q1;
        }
    }
    __syncthreads();
    if (tid < NC) {
        float s = 0.f, q = 0.f;
        #pragma unroll
        for (int t = 0; t < 4; t++) { s += sred[tid*4 + t]; q += sred[512 + tid*4 + t]; }
        g_psum[tid*NROWBLK + blockIdx.x] = s;
        g_psq [tid*NROWBLK + blockIdx.x] = q;
    }
}

// ---------------- BN stats ----------------
__global__ void k_bnstat(const float* __restrict__ gamma, const float* __restrict__ beta) {
    int c = blockIdx.x, tid = threadIdx.x;
    __shared__ float s1[256], s2[256];
    float a = 0.f, q = 0.f;
    for (int t = tid; t < NROWBLK; t += 256) { a += g_psum[c*NROWBLK + t]; q += g_psq[c*NROWBLK + t]; }
    s1[tid] = a; s2[tid] = q; __syncthreads();
    for (int s = 128; s > 0; s >>= 1) {
        if (tid < s) { s1[tid] += s1[tid+s]; s2[tid] += s2[tid+s]; }
        __syncthreads();
    }
    if (tid == 0) {
        const float invN = 1.0f / (float)(NB * NL);
        float mu  = s1[0] * invN;
        float var = s2[0] * invN - mu * mu;
        float rs  = rsqrtf(var + 1e-5f);
        float sc  = gamma[c] * rs;
        g_scale[c] = sc;
        g_shift[c] = beta[c] - mu * sc;
    }
}

// ---------------- normalize in place ----------------
__global__ __launch_bounds__(512) void k_norm(float* __restrict__ out) {
    int base = blockIdx.x * 1024 + threadIdx.x;
    #pragma unroll
    for (int r = 0; r < 2; r++) {
        int idx = base + (r << 9);
        float4 v = ((float4*)out)[idx];
        int c = (idx >> 12) & 127;
        float sc = g_scale[c], sh = g_shift[c];
        v.x = fmaf(v.x, sc, sh); v.y = fmaf(v.y, sc, sh);
        v.z = fmaf(v.z, sc, sh); v.w = fmaf(v.w, sc, sh);
        ((float4*)out)[idx] = v;
    }
}

// ---------------- launcher ----------------
extern "C" void kernel_launch(void* const* d_in, const int* in_sizes, int n_in,
                              void* d_out, int out_size) {
    const float* x            = (const float*)d_in[0];
    const float* w_spatial_in = (const float*)d_in[1];
    const float* w_dw_spatial = (const float*)d_in[2];
    const float* w_spatial_out= (const float*)d_in[3];
    const float* w_ch_in      = (const float*)d_in[4];
    const float* w_ch_dw      = (const float*)d_in[5];
    const float* w_ch_out     = (const float*)d_in[6];
    const float* w_mlp1       = (const float*)d_in[7];
    const float* b_mlp1       = (const float*)d_in[8];
    const float* w_mlp2       = (const float*)d_in[9];
    const float* b_mlp2       = (const float*)d_in[10];
    const float* diff_weight  = (const float*)d_in[11];
    const float* bn_gamma     = (const float*)d_in[12];
    const float* bn_beta      = (const float*)d_in[13];
    const float* w_out_proj   = (const float*)d_in[14];
    float* out = (float*)d_out;

    cudaFuncSetAttribute(k_gemm, cudaFuncAttributeMaxDynamicSharedMemorySize, GSMEM);

    k_build<<<NB*NC, 512>>>(x);     // also produces g_gap
    k_prepw<<<NC, 512>>>(w_out_proj, w_spatial_out, w_dw_spatial, w_spatial_in,
                         w_mlp2, b_mlp2, diff_weight);
    k_prep3<<<NB, 1024>>>(w_ch_in, w_ch_dw, w_ch_out, w_mlp1);
    k_vred <<<NB*8, 512>>>(x, b_mlp1);
    k_gemm <<<NROWBLK, 256, GSMEM>>>(x, out);
    k_bnstat<<<NC, 256>>>(bn_gamma, bn_beta);
    k_norm <<<NTOT/4/1024, 512>>>(out);
}

// round 14
// speedup vs baseline: 1.5179x; 1.5179x over previous
#include <cuda_runtime.h>
#include <math.h>
#include <stdint.h>

#define NB 8
#define NC 128
#define NH 128
#define NW 128
#define NL (NH*NW)          // 16384
#define NMID 32
#define KTOT 416
#define NPAN 13
#define NFROWS 288          // nsum(128) + diff(128) + silu(32)
#define NROWBLK 1024
#define NTOT (NB*NC*NL)
#define VT 256              // vred tile positions

// ---------------- device scratch ----------------
__device__ __align__(16) float g_Fg[(size_t)NB*NFROWS*NL];
__device__ float g_gap[NB][NC];
__device__ __align__(16) float g_Bt[KTOT*NC];
__device__ float g_ck[NB][3][NC];
__device__ float g_u[NB][NMID];
__device__ float g_b2p[NC];
__device__ float g_psum[NC*NROWBLK];
__device__ float g_psq[NC*NROWBLK];
__device__ float g_scale[NC];
__device__ float g_shift[NC];

// ---------------- helpers ----------------
__device__ __forceinline__ float to_tf32(float x) {
    uint32_t o;
    asm("cvt.rna.tf32.f32 %0, %1;" : "=r"(o) : "f"(x));
    return __uint_as_float(o);
}
__device__ __forceinline__ uint32_t cvt_rna_u(uint32_t x) {
    uint32_t o;
    asm("cvt.rna.tf32.f32 %0, %1;" : "=r"(o) : "f"(__uint_as_float(x)));
    return o;
}
__device__ __forceinline__ void mma_tf32(float* d, const uint32_t* a, const uint32_t* b) {
    asm volatile("mma.sync.aligned.m16n8k8.row.col.f32.tf32.tf32.f32 "
        "{%0,%1,%2,%3}, {%4,%5,%6,%7}, {%8,%9}, {%0,%1,%2,%3};"
        : "+f"(d[0]), "+f"(d[1]), "+f"(d[2]), "+f"(d[3])
        : "r"(a[0]), "r"(a[1]), "r"(a[2]), "r"(a[3]), "r"(b[0]), "r"(b[1]));
}
__device__ __forceinline__ uint32_t smem_u32(const void* p) {
    uint32_t a;
    asm("{ .reg .u64 t; cvta.to.shared.u64 t, %1; cvt.u32.u64 %0, t; }" : "=r"(a) : "l"(p));
    return a;
}
__device__ __forceinline__ void cp16(uint32_t d, const void* s, bool pred) {
    int sz = pred ? 16 : 0;
    asm volatile("cp.async.cg.shared.global [%0], [%1], 16, %2;"
                 :: "r"(d), "l"(s), "r"(sz) : "memory");
}
__device__ __forceinline__ void cp_commit() {
    asm volatile("cp.async.commit_group;" ::: "memory");
}
#define CP_WAIT(n) asm volatile("cp.async.wait_group %0;" :: "n"(n) : "memory")

// ---------------- fold weights — 512 threads, 4-way K split ----------------
__global__ __launch_bounds__(512) void k_prepw(
        const float* __restrict__ wp,  const float* __restrict__ wout,
        const float* __restrict__ wdw, const float* __restrict__ win,
        const float* __restrict__ w2,  const float* __restrict__ b2,
        const float* __restrict__ dwp) {
    const int o = blockIdx.x, tid = threadIdx.x;
    const int c = tid & 127, part = tid >> 7;
    __shared__ float wps[NC], q[NC];
    __shared__ float par[4][NC], parb[4][NC];
    if (tid < NC) wps[tid] = wp[o*NC + tid];
    __syncthreads();
    {
        float a = 0.f;
        const int t0 = part * 32;
        #pragma unroll 8
        for (int j = 0; j < 32; j++) a = fmaf(wps[t0+j], wout[(t0+j)*NC + c], a);
        par[part][c] = a;
    }
    __syncthreads();
    if (tid < NC) q[tid] = (par[0][tid] + par[1][tid]) + (par[2][tid] + par[3][tid]);
    __syncthreads();
    {
        const int t0 = part * 32;
        float a1 = 0.f, a2 = 0.f;
        #pragma unroll 8
        for (int j = 0; j < 32; j++) {
            int s = t0 + j;
            float qs = q[s];
            float w1v = wdw[s*3 + 1], w02 = wdw[s*3 + 0] + wdw[s*3 + 2];
            float wi = win[s*NC + c];
            a1 = fmaf(qs * w1v, wi, a1);
            a2 = fmaf(qs * w02, wi, a2);
        }
        par[part][c] = a1; parb[part][c] = a2;
    }
    __syncthreads();
    if (tid < NC) {
        float A1 = (par[0][tid] + par[1][tid]) + (par[2][tid] + par[3][tid]) + wps[tid];
        float A2 = 0.25f * ((parb[0][tid] + parb[1][tid]) + (parb[2][tid] + parb[3][tid]));
        g_Bt[tid*NC + o]          = to_tf32(A1);
        g_Bt[(NC + tid)*NC + o]   = to_tf32(A2);
        g_Bt[(2*NC + tid)*NC + o] = to_tf32(dwp[0] * wps[tid]);
    }
    __syncthreads();
    if (tid < NC) {
        int m = tid & 31, p4 = tid >> 5;
        float s4 = 0.f;
        const int t0 = p4 * 32;
        #pragma unroll 8
        for (int j = 0; j < 32; j++) s4 = fmaf(wps[t0+j], w2[(t0+j)*NMID + m], s4);
        par[p4][m] = s4;
        parb[0][tid] = wps[tid] * b2[tid];
    }
    __syncthreads();
    if (tid < 32) {
        g_Bt[(3*NC + tid)*NC + o] =
            to_tf32((par[0][tid] + par[1][tid]) + (par[2][tid] + par[3][tid]));
        float s = (parb[0][tid] + parb[0][tid+32]) + (parb[0][tid+64] + parb[0][tid+96]);
        for (int ofs = 16; ofs; ofs >>= 1) s += __shfl_xor_sync(0xffffffff, s, ofs);
        if (tid == 0) g_b2p[o] = s;
    }
}

// ---------------- per-batch vectors — 1024 threads, 8-way K split ----------------
__global__ __launch_bounds__(1024) void k_prep3(
        const float* __restrict__ wci, const float* __restrict__ wdwch,
        const float* __restrict__ wco, const float* __restrict__ w1) {
    const int b = blockIdx.x, tid = threadIdx.x;
    const int c = tid & 127, part = tid >> 7;
    __shared__ float gs[NC], g2s[NC];
    __shared__ float par[8][NC];
    __shared__ float par3[3][8][NC];
    __shared__ float nrm_s;
    if (tid < NC) { float g = g_gap[b][tid]; par[0][tid] = g * g; }
    __syncthreads();
    if (tid < 32) {
        float s = (par[0][tid] + par[0][tid+32]) + (par[0][tid+64] + par[0][tid+96]);
        for (int o = 16; o; o >>= 1) s += __shfl_xor_sync(0xffffffff, s, o);
        if (tid == 0) nrm_s = fmaxf(sqrtf(s), 1e-12f);
    }
    __syncthreads();
    if (tid < NC) gs[tid] = g_gap[b][tid] / nrm_s;
    __syncthreads();
    {
        float a = 0.f;
        const int t0 = part * 16;
        #pragma unroll
        for (int j = 0; j < 16; j++) a = fmaf(gs[t0+j], wco[(t0+j)*NC + c], a);
        par[part][c] = a;
    }
    __syncthreads();
    if (tid < NC) {
        float a = 0.f;
        #pragma unroll
        for (int p = 0; p < 8; p++) a += par[p][tid];
        g2s[tid] = a;
    }
    __syncthreads();
    {
        const int t0 = part * 16;
        float s0 = 0.f, s1 = 0.f, s2 = 0.f;
        #pragma unroll
        for (int j = 0; j < 16; j++) {
            int t = t0 + j;
            float wv = wci[t*NC + c] * g2s[t];
            s0 = fmaf(wv, wdwch[t*3 + 0], s0);
            s1 = fmaf(wv, wdwch[t*3 + 1], s1);
            s2 = fmaf(wv, wdwch[t*3 + 2], s2);
        }
        par3[0][part][c] = s0; par3[1][part][c] = s1; par3[2][part][c] = s2;
    }
    __syncthreads();
    if (tid < 384) {
        int k = tid >> 7, cc = tid & 127;
        float a = 0.f;
        #pragma unroll
        for (int p = 0; p < 8; p++) a += par3[k][p][cc];
        g_ck[b][k][cc] = a;
    }
    {
        int m = tid & 31, pt = tid >> 5;
        const int t0 = pt * 4;
        float s = 0.f;
        #pragma unroll
        for (int j = 0; j < 4; j++) s = fmaf(w1[m*NC + t0+j], gs[t0+j], s);
        ((float*)par)[pt*32 + m] = s;
    }
    __syncthreads();
    if (tid < NMID) {
        float s = 0.f;
        #pragma unroll
        for (int p = 0; p < 32; p++) s += ((float*)par)[p*32 + tid];
        g_u[b][tid] = s;
    }
}

// ---------------- stencil build + fused gap ----------------
__global__ __launch_bounds__(512) void k_build(const float* __restrict__ x) {
    __shared__ float red[512];
    const int bx = blockIdx.x;
    const int b = bx >> 7, c = bx & 127;
    const float* xp = x + (size_t)(b*NC + c) * NL;
    float* nrow = g_Fg + (size_t)b*NFROWS*NL + (size_t)c*NL;
    float* drow = nrow + (size_t)NC*NL;
    const int tid = threadIdx.x;
    float gsum = 0.f;
    #pragma unroll 2
    for (int r = 0; r < 8; r++) {
        int p4 = tid + (r << 9);
        int pos = p4 << 2;
        int i = pos >> 7, j0 = pos & 127;
        float4 c4 = ((const float4*)xp)[p4];
        gsum += (c4.x + c4.y) + (c4.z + c4.w);
        float lprev = (pos > 0) ? xp[pos-1] : 0.f;
        float rnext = (pos < NL-4) ? xp[pos+4] : 0.f;
        float u0,u1,u2,u3, d0,d1,d2,d3;
        if (i > 0) {
            float4 up4 = ((const float4*)xp)[p4-32];
            u0 = up4.x; u1 = up4.y; u2 = up4.z; u3 = up4.w;
        } else {
            u0 = (j0 > 0) ? xp[127*NW + j0-1] : 0.f;
            u1 = xp[127*NW + j0];
            u2 = xp[127*NW + j0+1];
            u3 = xp[127*NW + j0+2];
        }
        if (i < 127) {
            float4 dn4 = ((const float4*)xp)[p4+32];
            d0 = dn4.x; d1 = dn4.y; d2 = dn4.z; d3 = dn4.w;
        } else {
            d0 = xp[j0+1]; d1 = xp[j0+2]; d2 = xp[j0+3];
            d3 = (j0+3 < 127) ? xp[j0+4] : 0.f;
        }
        float l0 = lprev, l1 = c4.x, l2 = c4.y, l3 = c4.z;
        float r0 = c4.y, r1 = c4.z, r2 = c4.w, r3 = rnext;
        ((float4*)nrow)[p4] = make_float4(to_tf32((l0+r0)+(u0+d0)), to_tf32((l1+r1)+(u1+d1)),
                                          to_tf32((l2+r2)+(u2+d2)), to_tf32((l3+r3)+(u3+d3)));
        float lr0 = (j0 == 0) ? c4.y : lprev;
        float rr3 = (j0 == 124) ? c4.z : rnext;
        float ur0,ur1,ur2,ur3, dr0,dr1,dr2,dr3;
        if (i > 0) { ur0=u0; ur1=u1; ur2=u2; ur3=u3; }
        else       { ur0=d0; ur1=d1; ur2=d2; ur3=d3; }
        if (i < 127) { dr0=d0; dr1=d1; dr2=d2; dr3=d3; }
        else         { dr0=u0; dr1=u1; dr2=u2; dr3=u3; }
        float df0 = 0.25f*((fabsf(c4.x-lr0)+fabsf(c4.x-c4.y))+(fabsf(c4.x-ur0)+fabsf(c4.x-dr0)));
        float df1 = 0.25f*((fabsf(c4.y-c4.x)+fabsf(c4.y-c4.z))+(fabsf(c4.y-ur1)+fabsf(c4.y-dr1)));
        float df2 = 0.25f*((fabsf(c4.z-c4.y)+fabsf(c4.z-c4.w))+(fabsf(c4.z-ur2)+fabsf(c4.z-dr2)));
        float df3 = 0.25f*((fabsf(c4.w-c4.z)+fabsf(c4.w-rr3))+(fabsf(c4.w-ur3)+fabsf(c4.w-dr3)));
        ((float4*)drow)[p4] = make_float4(to_tf32(df0), to_tf32(df1), to_tf32(df2), to_tf32(df3));
    }
    red[tid] = gsum;
    __syncthreads();
    for (int k = 256; k > 0; k >>= 1) {
        if (tid < k) red[tid] += red[tid + k];
        __syncthreads();
    }
    if (tid == 0) g_gap[b][c] = red[0] * (1.0f / NL);
}

// ---------------- v reduction + silu: 512 blocks x 128 thr, channel-split float4 ----------------
__global__ __launch_bounds__(128) void k_vred(const float* __restrict__ x,
                                              const float* __restrict__ b1) {
    __shared__ float4 P0[2][64], P1[2][64], P2[2][64];
    __shared__ float s0f[VT+1], s1f[VT], s2f[VT+1];
    __shared__ float cks[3*NC], us[NMID], b1s[NMID];
    __shared__ float hLs[2], hRs[2];
    const int tid = threadIdx.x;
    const int b = blockIdx.x >> 6;
    const int tb = (blockIdx.x & 63) << 8;
    const int q = tid & 63, half = tid >> 6;
    const float* xb = x + (size_t)b * NC * NL;

    for (int t = tid; t < 3*NC; t += 128) cks[t] = (&g_ck[b][0][0])[t];
    if (tid < NMID) { us[tid] = g_u[b][tid]; b1s[tid] = b1[tid]; }
    __syncthreads();

    const int cb = half << 6;
    const float* base = xb + (size_t)cb * NL + tb;
    const bool hL = (q == 0)  && (tb > 0);
    const bool hR = (q == 63) && (tb + VT < NL);
    float a0x=0,a0y=0,a0z=0,a0w=0, a1x=0,a1y=0,a1z=0,a1w=0, a2x=0,a2y=0,a2z=0,a2w=0;
    float h = 0.f;
    #pragma unroll 4
    for (int c = 0; c < 64; c++) {
        float4 xv = ((const float4*)(base + (size_t)c * NL))[q];
        float k0 = cks[cb + c], k1 = cks[NC + cb + c], k2 = cks[2*NC + cb + c];
        a0x = fmaf(k0, xv.x, a0x); a0y = fmaf(k0, xv.y, a0y);
        a0z = fmaf(k0, xv.z, a0z); a0w = fmaf(k0, xv.w, a0w);
        a1x = fmaf(k1, xv.x, a1x); a1y = fmaf(k1, xv.y, a1y);
        a1z = fmaf(k1, xv.z, a1z); a1w = fmaf(k1, xv.w, a1w);
        a2x = fmaf(k2, xv.x, a2x); a2y = fmaf(k2, xv.y, a2y);
        a2z = fmaf(k2, xv.z, a2z); a2w = fmaf(k2, xv.w, a2w);
        if (hL) h = fmaf(k0, base[(size_t)c*NL - 1], h);
        if (hR) h = fmaf(k2, base[(size_t)c*NL + VT], h);
    }
    P0[half][q] = make_float4(a0x, a0y, a0z, a0w);
    P1[half][q] = make_float4(a1x, a1y, a1z, a1w);
    P2[half][q] = make_float4(a2x, a2y, a2z, a2w);
    if (q == 0)  hLs[half] = hL ? h : 0.f;
    if (q == 63) hRs[half] = hR ? h : 0.f;
    __syncthreads();
    if (tid < 64) {
        float4 u0 = P0[0][tid], v0 = P0[1][tid];
        float4 u1 = P1[0][tid], v1 = P1[1][tid];
        float4 u2 = P2[0][tid], v2 = P2[1][tid];
        int i0 = tid << 2;
        s0f[i0+1] = u0.x+v0.x; s0f[i0+2] = u0.y+v0.y; s0f[i0+3] = u0.z+v0.z; s0f[i0+4] = u0.w+v0.w;
        s1f[i0]   = u1.x+v1.x; s1f[i0+1] = u1.y+v1.y; s1f[i0+2] = u1.z+v1.z; s1f[i0+3] = u1.w+v1.w;
        s2f[i0]   = u2.x+v2.x; s2f[i0+1] = u2.y+v2.y; s2f[i0+2] = u2.z+v2.z; s2f[i0+3] = u2.w+v2.w;
        if (tid == 0)  s0f[0]  = hLs[0] + hLs[1];
        if (tid == 63) s2f[VT] = hRs[0] + hRs[1];
    }
    __syncthreads();
    {
        int i0 = q << 2;
        float v0 = s0f[i0]   + s1f[i0]   + s2f[i0+1];
        float v1 = s0f[i0+1] + s1f[i0+1] + s2f[i0+2];
        float v2 = s0f[i0+2] + s1f[i0+2] + s2f[i0+3];
        float v3 = s0f[i0+3] + s1f[i0+3] + s2f[i0+4];
        float* dst = g_Fg + (size_t)b*NFROWS*NL + (size_t)(2*NC)*NL + tb + i0;
        const int m0 = half << 4;
        #pragma unroll 4
        for (int m = m0; m < m0 + 16; m++) {
            float um = us[m], bm = b1s[m];
            float z0 = fmaf(um, v0, bm), z1 = fmaf(um, v1, bm);
            float z2 = fmaf(um, v2, bm), z3 = fmaf(um, v3, bm);
            *(float4*)(dst + (size_t)m * NL) = make_float4(
                to_tf32(z0 / (1.f + __expf(-z0))), to_tf32(z1 / (1.f + __expf(-z1))),
                to_tf32(z2 / (1.f + __expf(-z2))), to_tf32(z3 / (1.f + __expf(-z3))));
        }
    }
}

// ---------------- streaming GEMM (known-good), writes pre-BN to out ----------------
#define GSMEM (3*8192*4)

__global__ __launch_bounds__(256, 2) void k_gemm(const float* __restrict__ x,
                                                 float* __restrict__ out) {
    extern __shared__ __align__(16) float sm[];
    const int tid = threadIdx.x;
    const int b = blockIdx.x >> 7;
    const int posb = (blockIdx.x & 127) << 7;
    const float* xb  = x + (size_t)b * NC * NL + posb;
    const float* fgb = g_Fg + (size_t)b * NFROWS * NL + posb;

    auto issueP = [&](int p, int st) {
        int k0 = p * 32;
        const float* bsrc = (k0 < NC) ? (xb + (size_t)k0 * NL) : (fgb + (size_t)(k0 - NC) * NL);
        const float* asrc = g_Bt + k0 * NC;
        uint32_t ab = smem_u32(sm + st * 8192);
        uint32_t bb = ab + 16384;
        #pragma unroll
        for (int r = 0; r < 4; r++) {
            int f = tid + (r << 8);
            int kr = f >> 5, j4 = f & 31;
            int sw = (kr*32 + (j4 ^ ((kr & 3) << 1))) * 16;
            cp16(ab + sw, asrc + kr*NC + (j4 << 2), true);
            cp16(bb + sw, bsrc + (size_t)kr*NL + (j4 << 2), true);
        }
        cp_commit();
    };
    issueP(0, 0); issueP(1, 1);

    const int lane = tid & 31, g = lane >> 2, tg = lane & 3;
    const int w = tid >> 5, mbase = (w >> 2) * 64, nbase = (w & 3) * 32;
    const int swa = tg << 3;
    float dacc[4][4][4];
    #pragma unroll
    for (int mt = 0; mt < 4; mt++)
        #pragma unroll
        for (int nt = 0; nt < 4; nt++)
            #pragma unroll
            for (int qq = 0; qq < 4; qq++) dacc[mt][nt][qq] = 0.f;

    auto mmaPanel = [&](const uint32_t* As, bool cvt) {
        const uint32_t* Fu = As + 4096;
        #pragma unroll
        for (int ks = 0; ks < 4; ks++) {
            const int kr = ks * 8;
            uint32_t af[4][4], bf[4][2];
            #pragma unroll
            for (int nt = 0; nt < 4; nt++) {
                int n = nbase + nt*8 + g;
                uint32_t v0 = Fu[(kr + tg)*128 + (n ^ swa)];
                uint32_t v1 = Fu[(kr + tg + 4)*128 + (n ^ swa)];
                bf[nt][0] = cvt ? cvt_rna_u(v0) : v0;
                bf[nt][1] = cvt ? cvt_rna_u(v1) : v1;
            }
            #pragma unroll
            for (int mt = 0; mt < 4; mt++) {
                int o = mbase + mt*16 + g;
                af[mt][0] = As[(kr + tg)*128 + (o ^ swa)];
                af[mt][1] = As[(kr + tg)*128 + ((o+8) ^ swa)];
                af[mt][2] = As[(kr + tg + 4)*128 + (o ^ swa)];
                af[mt][3] = As[(kr + tg + 4)*128 + ((o+8) ^ swa)];
            }
            #pragma unroll
            for (int mt = 0; mt < 4; mt++)
                #pragma unroll
                for (int nt = 0; nt < 4; nt++)
                    mma_tf32(dacc[mt][nt], af[mt], bf[nt]);
        }
    };

    int st = 0;
    #pragma unroll 1
    for (int p = 0; p < NPAN; p++) {
        if (p < NPAN-1) { CP_WAIT(1); } else { CP_WAIT(0); }
        __syncthreads();
        if (p + 2 < NPAN) issueP(p + 2, (p + 2) % 3);
        mmaPanel((const uint32_t*)(sm + st * 8192), p < 4);
        st = (st == 2) ? 0 : st + 1;
    }
    __syncthreads();

    // ---- epilogue: bias, pre-BN store to out, BN partials ----
    float* sred = sm;
    #pragma unroll
    for (int mt = 0; mt < 4; mt++) {
        int o0 = mbase + mt*16 + g, o1 = o0 + 8;
        float bb0 = g_b2p[o0], bb1 = g_b2p[o1];
        float* row0 = &out[(size_t)(b*NC + o0) * NL + posb];
        float* row1 = &out[(size_t)(b*NC + o1) * NL + posb];
        float s0 = 0.f, q0 = 0.f, s1 = 0.f, q1 = 0.f;
        #pragma unroll
        for (int nt = 0; nt < 4; nt++) {
            float v0 = dacc[mt][nt][0] + bb0, v1 = dacc[mt][nt][1] + bb0;
            float v2 = dacc[mt][nt][2] + bb1, v3 = dacc[mt][nt][3] + bb1;
            int j = nbase + nt*8 + 2*tg;
            *(float2*)(row0 + j) = make_float2(v0, v1);
            *(float2*)(row1 + j) = make_float2(v2, v3);
            s0 += v0 + v1; q0 = fmaf(v0, v0, q0); q0 = fmaf(v1, v1, q0);
            s1 += v2 + v3; q1 = fmaf(v2, v2, q1); q1 = fmaf(v3, v3, q1);
        }
        s0 += __shfl_xor_sync(0xffffffff, s0, 1); s0 += __shfl_xor_sync(0xffffffff, s0, 2);
        q0 += __shfl_xor_sync(0xffffffff, q0, 1); q0 += __shfl_xor_sync(0xffffffff, q0, 2);
        s1 += __shfl_xor_sync(0xffffffff, s1, 1); s1 += __shfl_xor_sync(0xffffffff, s1, 2);
        q1 += __shfl_xor_sync(0xffffffff, q1, 1); q1 += __shfl_xor_sync(0xffffffff, q1, 2);
        if (tg == 0) {
            int nwq = w & 3;
            sred[o0*4 + nwq] = s0; sred[512 + o0*4 + nwq] = q0;
            sred[o1*4 + nwq] = s1; sred[512 + o1*4 + nwq] = q1;
        }
    }
    __syncthreads();
    if (tid < NC) {
        float s = 0.f, q = 0.f;
        #pragma unroll
        for (int t = 0; t < 4; t++) { s += sred[tid*4 + t]; q += sred[512 + tid*4 + t]; }
        g_psum[tid*NROWBLK + blockIdx.x] = s;
        g_psq [tid*NROWBLK + blockIdx.x] = q;
    }
}

// ---------------- BN stats ----------------
__global__ void k_bnstat(const float* __restrict__ gamma, const float* __restrict__ beta) {
    int c = blockIdx.x, tid = threadIdx.x;
    __shared__ float s1[256], s2[256];
    float a = 0.f, q = 0.f;
    for (int t = tid; t < NROWBLK; t += 256) { a += g_psum[c*NROWBLK + t]; q += g_psq[c*NROWBLK + t]; }
    s1[tid] = a; s2[tid] = q; __syncthreads();
    for (int s = 128; s > 0; s >>= 1) {
        if (tid < s) { s1[tid] += s1[tid+s]; s2[tid] += s2[tid+s]; }
        __syncthreads();
    }
    if (tid == 0) {
        const float invN = 1.0f / (float)(NB * NL);
        float mu  = s1[0] * invN;
        float var = s2[0] * invN - mu * mu;
        float rs  = rsqrtf(var + 1e-5f);
        float sc  = gamma[c] * rs;
        g_scale[c] = sc;
        g_shift[c] = beta[c] - mu * sc;
    }
}

// ---------------- normalize in place ----------------
__global__ __launch_bounds__(512) void k_norm(float* __restrict__ out) {
    int base = blockIdx.x * 1024 + threadIdx.x;
    #pragma unroll
    for (int r = 0; r < 2; r++) {
        int idx = base + (r << 9);
        float4 v = ((float4*)out)[idx];
        int c = (idx >> 12) & 127;
        float sc = g_scale[c], sh = g_shift[c];
        v.x = fmaf(v.x, sc, sh); v.y = fmaf(v.y, sc, sh);
        v.z = fmaf(v.z, sc, sh); v.w = fmaf(v.w, sc, sh);
        ((float4*)out)[idx] = v;
    }
}

// ---------------- launcher ----------------
extern "C" void kernel_launch(void* const* d_in, const int* in_sizes, int n_in,
                              void* d_out, int out_size) {
    const float* x            = (const float*)d_in[0];
    const float* w_spatial_in = (const float*)d_in[1];
    const float* w_dw_spatial = (const float*)d_in[2];
    const float* w_spatial_out= (const float*)d_in[3];
    const float* w_ch_in      = (const float*)d_in[4];
    const float* w_ch_dw      = (const float*)d_in[5];
    const float* w_ch_out     = (const float*)d_in[6];
    const float* w_mlp1       = (const float*)d_in[7];
    const float* b_mlp1       = (const float*)d_in[8];
    const float* w_mlp2       = (const float*)d_in[9];
    const float* b_mlp2       = (const float*)d_in[10];
    const float* diff_weight  = (const float*)d_in[11];
    const float* bn_gamma     = (const float*)d_in[12];
    const float* bn_beta      = (const float*)d_in[13];
    const float* w_out_proj   = (const float*)d_in[14];
    float* out = (float*)d_out;

    cudaFuncSetAttribute(k_gemm, cudaFuncAttributeMaxDynamicSharedMemorySize, GSMEM);

    k_build<<<NB*NC, 512>>>(x);     // also produces g_gap
    k_prepw<<<NC, 512>>>(w_out_proj, w_spatial_out, w_dw_spatial, w_spatial_in,
                         w_mlp2, b_mlp2, diff_weight);
    k_prep3<<<NB, 1024>>>(w_ch_in, w_ch_dw, w_ch_out, w_mlp1);
    k_vred <<<NB*64, 128>>>(x, b_mlp1);
    k_gemm <<<NROWBLK, 256, GSMEM>>>(x, out);
    k_bnstat<<<NC, 256>>>(bn_gamma, bn_beta);
    k_norm <<<NTOT/4/1024, 512>>>(out);
}

// round 15
// speedup vs baseline: 1.6842x; 1.1096x over previous
#include <cuda_runtime.h>
#include <math.h>
#include <stdint.h>

#define NB 8
#define NC 128
#define NH 128
#define NW 128
#define NL (NH*NW)          // 16384
#define NMID 32
#define KTOT 416
#define NPAN 13
#define NFROWS 288          // nsum(128) + diff(128) + silu(32)
#define NROWBLK 1024
#define NTOT (NB*NC*NL)
#define VT 256              // vred tile positions

// ---------------- device scratch ----------------
__device__ __align__(16) float g_Fg[(size_t)NB*NFROWS*NL];
__device__ float g_gap[NB][NC];
__device__ __align__(16) float g_Bt[KTOT*NC];
__device__ float g_ck[NB][3][NC];
__device__ float g_u[NB][NMID];
__device__ float g_b2p[NC];
__device__ float g_psum[NC*NROWBLK];
__device__ float g_psq[NC*NROWBLK];
__device__ float g_scale[NC];
__device__ float g_shift[NC];

// ---------------- helpers ----------------
__device__ __forceinline__ float to_tf32(float x) {
    uint32_t o;
    asm("cvt.rna.tf32.f32 %0, %1;" : "=r"(o) : "f"(x));
    return __uint_as_float(o);
}
__device__ __forceinline__ uint32_t cvt_rna_u(uint32_t x) {
    uint32_t o;
    asm("cvt.rna.tf32.f32 %0, %1;" : "=r"(o) : "f"(__uint_as_float(x)));
    return o;
}
__device__ __forceinline__ void mma_tf32(float* d, const uint32_t* a, const uint32_t* b) {
    asm volatile("mma.sync.aligned.m16n8k8.row.col.f32.tf32.tf32.f32 "
        "{%0,%1,%2,%3}, {%4,%5,%6,%7}, {%8,%9}, {%0,%1,%2,%3};"
        : "+f"(d[0]), "+f"(d[1]), "+f"(d[2]), "+f"(d[3])
        : "r"(a[0]), "r"(a[1]), "r"(a[2]), "r"(a[3]), "r"(b[0]), "r"(b[1]));
}
__device__ __forceinline__ uint32_t smem_u32(const void* p) {
    uint32_t a;
    asm("{ .reg .u64 t; cvta.to.shared.u64 t, %1; cvt.u32.u64 %0, t; }" : "=r"(a) : "l"(p));
    return a;
}
__device__ __forceinline__ void cp16(uint32_t d, const void* s, bool pred) {
    int sz = pred ? 16 : 0;
    asm volatile("cp.async.cg.shared.global [%0], [%1], 16, %2;"
                 :: "r"(d), "l"(s), "r"(sz) : "memory");
}
__device__ __forceinline__ void cp_commit() {
    asm volatile("cp.async.commit_group;" ::: "memory");
}
#define CP_WAIT(n) asm volatile("cp.async.wait_group %0;" :: "n"(n) : "memory")

// ---------------- fold weights — 512 threads, 4-way K split ----------------
__global__ __launch_bounds__(512) void k_prepw(
        const float* __restrict__ wp,  const float* __restrict__ wout,
        const float* __restrict__ wdw, const float* __restrict__ win,
        const float* __restrict__ w2,  const float* __restrict__ b2,
        const float* __restrict__ dwp) {
    const int o = blockIdx.x, tid = threadIdx.x;
    const int c = tid & 127, part = tid >> 7;
    __shared__ float wps[NC], q[NC];
    __shared__ float par[4][NC], parb[4][NC];
    if (tid < NC) wps[tid] = wp[o*NC + tid];
    __syncthreads();
    {
        float a = 0.f;
        const int t0 = part * 32;
        #pragma unroll 8
        for (int j = 0; j < 32; j++) a = fmaf(wps[t0+j], wout[(t0+j)*NC + c], a);
        par[part][c] = a;
    }
    __syncthreads();
    if (tid < NC) q[tid] = (par[0][tid] + par[1][tid]) + (par[2][tid] + par[3][tid]);
    __syncthreads();
    {
        const int t0 = part * 32;
        float a1 = 0.f, a2 = 0.f;
        #pragma unroll 8
        for (int j = 0; j < 32; j++) {
            int s = t0 + j;
            float qs = q[s];
            float w1v = wdw[s*3 + 1], w02 = wdw[s*3 + 0] + wdw[s*3 + 2];
            float wi = win[s*NC + c];
            a1 = fmaf(qs * w1v, wi, a1);
            a2 = fmaf(qs * w02, wi, a2);
        }
        par[part][c] = a1; parb[part][c] = a2;
    }
    __syncthreads();
    if (tid < NC) {
        float A1 = (par[0][tid] + par[1][tid]) + (par[2][tid] + par[3][tid]) + wps[tid];
        float A2 = 0.25f * ((parb[0][tid] + parb[1][tid]) + (parb[2][tid] + parb[3][tid]));
        g_Bt[tid*NC + o]          = to_tf32(A1);
        g_Bt[(NC + tid)*NC + o]   = to_tf32(A2);
        g_Bt[(2*NC + tid)*NC + o] = to_tf32(dwp[0] * wps[tid]);
    }
    __syncthreads();
    if (tid < NC) {
        int m = tid & 31, p4 = tid >> 5;
        float s4 = 0.f;
        const int t0 = p4 * 32;
        #pragma unroll 8
        for (int j = 0; j < 32; j++) s4 = fmaf(wps[t0+j], w2[(t0+j)*NMID + m], s4);
        par[p4][m] = s4;
        parb[0][tid] = wps[tid] * b2[tid];
    }
    __syncthreads();
    if (tid < 32) {
        g_Bt[(3*NC + tid)*NC + o] =
            to_tf32((par[0][tid] + par[1][tid]) + (par[2][tid] + par[3][tid]));
        float s = (parb[0][tid] + parb[0][tid+32]) + (parb[0][tid+64] + parb[0][tid+96]);
        for (int ofs = 16; ofs; ofs >>= 1) s += __shfl_xor_sync(0xffffffff, s, ofs);
        if (tid == 0) g_b2p[o] = s;
    }
}

// ---------------- per-batch vectors — 1024 threads, 8-way K split ----------------
__global__ __launch_bounds__(1024) void k_prep3(
        const float* __restrict__ wci, const float* __restrict__ wdwch,
        const float* __restrict__ wco, const float* __restrict__ w1) {
    const int b = blockIdx.x, tid = threadIdx.x;
    const int c = tid & 127, part = tid >> 7;
    __shared__ float gs[NC], g2s[NC];
    __shared__ float par[8][NC];
    __shared__ float par3[3][8][NC];
    __shared__ float nrm_s;
    if (tid < NC) { float g = g_gap[b][tid]; par[0][tid] = g * g; }
    __syncthreads();
    if (tid < 32) {
        float s = (par[0][tid] + par[0][tid+32]) + (par[0][tid+64] + par[0][tid+96]);
        for (int o = 16; o; o >>= 1) s += __shfl_xor_sync(0xffffffff, s, o);
        if (tid == 0) nrm_s = fmaxf(sqrtf(s), 1e-12f);
    }
    __syncthreads();
    if (tid < NC) gs[tid] = g_gap[b][tid] / nrm_s;
    __syncthreads();
    {
        float a = 0.f;
        const int t0 = part * 16;
        #pragma unroll
        for (int j = 0; j < 16; j++) a = fmaf(gs[t0+j], wco[(t0+j)*NC + c], a);
        par[part][c] = a;
    }
    __syncthreads();
    if (tid < NC) {
        float a = 0.f;
        #pragma unroll
        for (int p = 0; p < 8; p++) a += par[p][tid];
        g2s[tid] = a;
    }
    __syncthreads();
    {
        const int t0 = part * 16;
        float s0 = 0.f, s1 = 0.f, s2 = 0.f;
        #pragma unroll
        for (int j = 0; j < 16; j++) {
            int t = t0 + j;
            float wv = wci[t*NC + c] * g2s[t];
            s0 = fmaf(wv, wdwch[t*3 + 0], s0);
            s1 = fmaf(wv, wdwch[t*3 + 1], s1);
            s2 = fmaf(wv, wdwch[t*3 + 2], s2);
        }
        par3[0][part][c] = s0; par3[1][part][c] = s1; par3[2][part][c] = s2;
    }
    __syncthreads();
    if (tid < 384) {
        int k = tid >> 7, cc = tid & 127;
        float a = 0.f;
        #pragma unroll
        for (int p = 0; p < 8; p++) a += par3[k][p][cc];
        g_ck[b][k][cc] = a;
    }
    {
        int m = tid & 31, pt = tid >> 5;
        const int t0 = pt * 4;
        float s = 0.f;
        #pragma unroll
        for (int j = 0; j < 4; j++) s = fmaf(w1[m*NC + t0+j], gs[t0+j], s);
        ((float*)par)[pt*32 + m] = s;
    }
    __syncthreads();
    if (tid < NMID) {
        float s = 0.f;
        #pragma unroll
        for (int p = 0; p < 32; p++) s += ((float*)par)[p*32 + tid];
        g_u[b][tid] = s;
    }
}

// ---------------- stencil build + fused gap ----------------
__global__ __launch_bounds__(512) void k_build(const float* __restrict__ x) {
    __shared__ float red[512];
    const int bx = blockIdx.x;
    const int b = bx >> 7, c = bx & 127;
    const float* xp = x + (size_t)(b*NC + c) * NL;
    float* nrow = g_Fg + (size_t)b*NFROWS*NL + (size_t)c*NL;
    float* drow = nrow + (size_t)NC*NL;
    const int tid = threadIdx.x;
    float gsum = 0.f;
    #pragma unroll 2
    for (int r = 0; r < 8; r++) {
        int p4 = tid + (r << 9);
        int pos = p4 << 2;
        int i = pos >> 7, j0 = pos & 127;
        float4 c4 = ((const float4*)xp)[p4];
        gsum += (c4.x + c4.y) + (c4.z + c4.w);
        float lprev = (pos > 0) ? xp[pos-1] : 0.f;
        float rnext = (pos < NL-4) ? xp[pos+4] : 0.f;
        float u0,u1,u2,u3, d0,d1,d2,d3;
        if (i > 0) {
            float4 up4 = ((const float4*)xp)[p4-32];
            u0 = up4.x; u1 = up4.y; u2 = up4.z; u3 = up4.w;
        } else {
            u0 = (j0 > 0) ? xp[127*NW + j0-1] : 0.f;
            u1 = xp[127*NW + j0];
            u2 = xp[127*NW + j0+1];
            u3 = xp[127*NW + j0+2];
        }
        if (i < 127) {
            float4 dn4 = ((const float4*)xp)[p4+32];
            d0 = dn4.x; d1 = dn4.y; d2 = dn4.z; d3 = dn4.w;
        } else {
            d0 = xp[j0+1]; d1 = xp[j0+2]; d2 = xp[j0+3];
            d3 = (j0+3 < 127) ? xp[j0+4] : 0.f;
        }
        float l0 = lprev, l1 = c4.x, l2 = c4.y, l3 = c4.z;
        float r0 = c4.y, r1 = c4.z, r2 = c4.w, r3 = rnext;
        ((float4*)nrow)[p4] = make_float4(to_tf32((l0+r0)+(u0+d0)), to_tf32((l1+r1)+(u1+d1)),
                                          to_tf32((l2+r2)+(u2+d2)), to_tf32((l3+r3)+(u3+d3)));
        float lr0 = (j0 == 0) ? c4.y : lprev;
        float rr3 = (j0 == 124) ? c4.z : rnext;
        float ur0,ur1,ur2,ur3, dr0,dr1,dr2,dr3;
        if (i > 0) { ur0=u0; ur1=u1; ur2=u2; ur3=u3; }
        else       { ur0=d0; ur1=d1; ur2=d2; ur3=d3; }
        if (i < 127) { dr0=d0; dr1=d1; dr2=d2; dr3=d3; }
        else         { dr0=u0; dr1=u1; dr2=u2; dr3=u3; }
        float df0 = 0.25f*((fabsf(c4.x-lr0)+fabsf(c4.x-c4.y))+(fabsf(c4.x-ur0)+fabsf(c4.x-dr0)));
        float df1 = 0.25f*((fabsf(c4.y-c4.x)+fabsf(c4.y-c4.z))+(fabsf(c4.y-ur1)+fabsf(c4.y-dr1)));
        float df2 = 0.25f*((fabsf(c4.z-c4.y)+fabsf(c4.z-c4.w))+(fabsf(c4.z-ur2)+fabsf(c4.z-dr2)));
        float df3 = 0.25f*((fabsf(c4.w-c4.z)+fabsf(c4.w-rr3))+(fabsf(c4.w-ur3)+fabsf(c4.w-dr3)));
        ((float4*)drow)[p4] = make_float4(to_tf32(df0), to_tf32(df1), to_tf32(df2), to_tf32(df3));
    }
    red[tid] = gsum;
    __syncthreads();
    for (int k = 256; k > 0; k >>= 1) {
        if (tid < k) red[tid] += red[tid + k];
        __syncthreads();
    }
    if (tid == 0) g_gap[b][c] = red[0] * (1.0f / NL);
}

// ---------------- v reduction + silu: 512 blocks x 256 thr, 4-way channel split ----------------
__global__ __launch_bounds__(256) void k_vred(const float* __restrict__ x,
                                              const float* __restrict__ b1) {
    __shared__ float4 P0[4][64], P1[4][64], P2[4][64];   // 12KB
    __shared__ float s0f[VT+1], s1f[VT], s2f[VT+1];
    __shared__ float cks[3*NC], us[NMID], b1s[NMID];
    __shared__ float hLs[4], hRs[4];
    const int tid = threadIdx.x;
    const int b = blockIdx.x >> 6;
    const int tb = (blockIdx.x & 63) << 8;
    const int q = tid & 63, part = tid >> 6;
    const float* xb = x + (size_t)b * NC * NL;

    for (int t = tid; t < 3*NC; t += 256) cks[t] = (&g_ck[b][0][0])[t];
    if (tid < NMID) { us[tid] = g_u[b][tid]; b1s[tid] = b1[tid]; }
    __syncthreads();

    const int cb = part << 5;                 // 32 channels per part
    const float* base = xb + (size_t)cb * NL + tb;
    const bool hL = (q == 0)  && (tb > 0);
    const bool hR = (q == 63) && (tb + VT < NL);
    float a0x=0,a0y=0,a0z=0,a0w=0, a1x=0,a1y=0,a1z=0,a1w=0, a2x=0,a2y=0,a2z=0,a2w=0;
    float h = 0.f;
    #pragma unroll 8
    for (int c = 0; c < 32; c++) {
        float4 xv = ((const float4*)(base + (size_t)c * NL))[q];
        float k0 = cks[cb + c], k1 = cks[NC + cb + c], k2 = cks[2*NC + cb + c];
        a0x = fmaf(k0, xv.x, a0x); a0y = fmaf(k0, xv.y, a0y);
        a0z = fmaf(k0, xv.z, a0z); a0w = fmaf(k0, xv.w, a0w);
        a1x = fmaf(k1, xv.x, a1x); a1y = fmaf(k1, xv.y, a1y);
        a1z = fmaf(k1, xv.z, a1z); a1w = fmaf(k1, xv.w, a1w);
        a2x = fmaf(k2, xv.x, a2x); a2y = fmaf(k2, xv.y, a2y);
        a2z = fmaf(k2, xv.z, a2z); a2w = fmaf(k2, xv.w, a2w);
        if (hL) h = fmaf(k0, base[(size_t)c*NL - 1], h);
        if (hR) h = fmaf(k2, base[(size_t)c*NL + VT], h);
    }
    P0[part][q] = make_float4(a0x, a0y, a0z, a0w);
    P1[part][q] = make_float4(a1x, a1y, a1z, a1w);
    P2[part][q] = make_float4(a2x, a2y, a2z, a2w);
    if (q == 0)  hLs[part] = hL ? h : 0.f;
    if (q == 63) hRs[part] = hR ? h : 0.f;
    __syncthreads();
    if (tid < 64) {
        float4 t0 = P0[0][tid], t1 = P0[1][tid], t2 = P0[2][tid], t3 = P0[3][tid];
        float4 u0 = P1[0][tid], u1 = P1[1][tid], u2 = P1[2][tid], u3 = P1[3][tid];
        float4 w0 = P2[0][tid], w1 = P2[1][tid], w2 = P2[2][tid], w3 = P2[3][tid];
        int i0 = tid << 2;
        s0f[i0+1] = (t0.x+t1.x)+(t2.x+t3.x); s0f[i0+2] = (t0.y+t1.y)+(t2.y+t3.y);
        s0f[i0+3] = (t0.z+t1.z)+(t2.z+t3.z); s0f[i0+4] = (t0.w+t1.w)+(t2.w+t3.w);
        s1f[i0]   = (u0.x+u1.x)+(u2.x+u3.x); s1f[i0+1] = (u0.y+u1.y)+(u2.y+u3.y);
        s1f[i0+2] = (u0.z+u1.z)+(u2.z+u3.z); s1f[i0+3] = (u0.w+u1.w)+(u2.w+u3.w);
        s2f[i0]   = (w0.x+w1.x)+(w2.x+w3.x); s2f[i0+1] = (w0.y+w1.y)+(w2.y+w3.y);
        s2f[i0+2] = (w0.z+w1.z)+(w2.z+w3.z); s2f[i0+3] = (w0.w+w1.w)+(w2.w+w3.w);
        if (tid == 0)  s0f[0]  = (hLs[0]+hLs[1])+(hLs[2]+hLs[3]);
        if (tid == 63) s2f[VT] = (hRs[0]+hRs[1])+(hRs[2]+hRs[3]);
    }
    __syncthreads();
    {
        int i0 = q << 2;
        float v0 = s0f[i0]   + s1f[i0]   + s2f[i0+1];
        float v1 = s0f[i0+1] + s1f[i0+1] + s2f[i0+2];
        float v2 = s0f[i0+2] + s1f[i0+2] + s2f[i0+3];
        float v3 = s0f[i0+3] + s1f[i0+3] + s2f[i0+4];
        float* dst = g_Fg + (size_t)b*NFROWS*NL + (size_t)(2*NC)*NL + tb + i0;
        const int m0 = part << 3;             // 8 silu rows per part
        #pragma unroll 4
        for (int m = m0; m < m0 + 8; m++) {
            float um = us[m], bm = b1s[m];
            float z0 = fmaf(um, v0, bm), z1 = fmaf(um, v1, bm);
            float z2 = fmaf(um, v2, bm), z3 = fmaf(um, v3, bm);
            *(float4*)(dst + (size_t)m * NL) = make_float4(
                to_tf32(z0 / (1.f + __expf(-z0))), to_tf32(z1 / (1.f + __expf(-z1))),
                to_tf32(z2 / (1.f + __expf(-z2))), to_tf32(z3 / (1.f + __expf(-z3))));
        }
    }
}

// ---------------- streaming GEMM (known-good), writes pre-BN to out ----------------
#define GSMEM (3*8192*4)

__global__ __launch_bounds__(256, 2) void k_gemm(const float* __restrict__ x,
                                                 float* __restrict__ out) {
    extern __shared__ __align__(16) float sm[];
    const int tid = threadIdx.x;
    const int b = blockIdx.x >> 7;
    const int posb = (blockIdx.x & 127) << 7;
    const float* xb  = x + (size_t)b * NC * NL + posb;
    const float* fgb = g_Fg + (size_t)b * NFROWS * NL + posb;

    auto issueP = [&](int p, int st) {
        int k0 = p * 32;
        const float* bsrc = (k0 < NC) ? (xb + (size_t)k0 * NL) : (fgb + (size_t)(k0 - NC) * NL);
        const float* asrc = g_Bt + k0 * NC;
        uint32_t ab = smem_u32(sm + st * 8192);
        uint32_t bb = ab + 16384;
        #pragma unroll
        for (int r = 0; r < 4; r++) {
            int f = tid + (r << 8);
            int kr = f >> 5, j4 = f & 31;
            int sw = (kr*32 + (j4 ^ ((kr & 3) << 1))) * 16;
            cp16(ab + sw, asrc + kr*NC + (j4 << 2), true);
            cp16(bb + sw, bsrc + (size_t)kr*NL + (j4 << 2), true);
        }
        cp_commit();
    };
    issueP(0, 0); issueP(1, 1);

    const int lane = tid & 31, g = lane >> 2, tg = lane & 3;
    const int w = tid >> 5, mbase = (w >> 2) * 64, nbase = (w & 3) * 32;
    const int swa = tg << 3;
    float dacc[4][4][4];
    #pragma unroll
    for (int mt = 0; mt < 4; mt++)
        #pragma unroll
        for (int nt = 0; nt < 4; nt++)
            #pragma unroll
            for (int qq = 0; qq < 4; qq++) dacc[mt][nt][qq] = 0.f;

    auto mmaPanel = [&](const uint32_t* As, bool cvt) {
        const uint32_t* Fu = As + 4096;
        #pragma unroll
        for (int ks = 0; ks < 4; ks++) {
            const int kr = ks * 8;
            uint32_t af[4][4], bf[4][2];
            #pragma unroll
            for (int nt = 0; nt < 4; nt++) {
                int n = nbase + nt*8 + g;
                uint32_t v0 = Fu[(kr + tg)*128 + (n ^ swa)];
                uint32_t v1 = Fu[(kr + tg + 4)*128 + (n ^ swa)];
                bf[nt][0] = cvt ? cvt_rna_u(v0) : v0;
                bf[nt][1] = cvt ? cvt_rna_u(v1) : v1;
            }
            #pragma unroll
            for (int mt = 0; mt < 4; mt++) {
                int o = mbase + mt*16 + g;
                af[mt][0] = As[(kr + tg)*128 + (o ^ swa)];
                af[mt][1] = As[(kr + tg)*128 + ((o+8) ^ swa)];
                af[mt][2] = As[(kr + tg + 4)*128 + (o ^ swa)];
                af[mt][3] = As[(kr + tg + 4)*128 + ((o+8) ^ swa)];
            }
            #pragma unroll
            for (int mt = 0; mt < 4; mt++)
                #pragma unroll
                for (int nt = 0; nt < 4; nt++)
                    mma_tf32(dacc[mt][nt], af[mt], bf[nt]);
        }
    };

    int st = 0;
    #pragma unroll 1
    for (int p = 0; p < NPAN; p++) {
        if (p < NPAN-1) { CP_WAIT(1); } else { CP_WAIT(0); }
        __syncthreads();
        if (p + 2 < NPAN) issueP(p + 2, (p + 2) % 3);
        mmaPanel((const uint32_t*)(sm + st * 8192), p < 4);
        st = (st == 2) ? 0 : st + 1;
    }
    __syncthreads();

    // ---- epilogue: bias, pre-BN store to out, BN partials ----
    float* sred = sm;
    #pragma unroll
    for (int mt = 0; mt < 4; mt++) {
        int o0 = mbase + mt*16 + g, o1 = o0 + 8;
        float bb0 = g_b2p[o0], bb1 = g_b2p[o1];
        float* row0 = &out[(size_t)(b*NC + o0) * NL + posb];
        float* row1 = &out[(size_t)(b*NC + o1) * NL + posb];
        float s0 = 0.f, q0 = 0.f, s1 = 0.f, q1 = 0.f;
        #pragma unroll
        for (int nt = 0; nt < 4; nt++) {
            float v0 = dacc[mt][nt][0] + bb0, v1 = dacc[mt][nt][1] + bb0;
            float v2 = dacc[mt][nt][2] + bb1, v3 = dacc[mt][nt][3] + bb1;
            int j = nbase + nt*8 + 2*tg;
            *(float2*)(row0 + j) = make_float2(v0, v1);
            *(float2*)(row1 + j) = make_float2(v2, v3);
            s0 += v0 + v1; q0 = fmaf(v0, v0, q0); q0 = fmaf(v1, v1, q0);
            s1 += v2 + v3; q1 = fmaf(v2, v2, q1); q1 = fmaf(v3, v3, q1);
        }
        s0 += __shfl_xor_sync(0xffffffff, s0, 1); s0 += __shfl_xor_sync(0xffffffff, s0, 2);
        q0 += __shfl_xor_sync(0xffffffff, q0, 1); q0 += __shfl_xor_sync(0xffffffff, q0, 2);
        s1 += __shfl_xor_sync(0xffffffff, s1, 1); s1 += __shfl_xor_sync(0xffffffff, s1, 2);
        q1 += __shfl_xor_sync(0xffffffff, q1, 1); q1 += __shfl_xor_sync(0xffffffff, q1, 2);
        if (tg == 0) {
            int nwq = w & 3;
            sred[o0*4 + nwq] = s0; sred[512 + o0*4 + nwq] = q0;
            sred[o1*4 + nwq] = s1; sred[512 + o1*4 + nwq] = q1;
        }
    }
    __syncthreads();
    if (tid < NC) {
        float s = 0.f, q = 0.f;
        #pragma unroll
        for (int t = 0; t < 4; t++) { s += sred[tid*4 + t]; q += sred[512 + tid*4 + t]; }
        g_psum[tid*NROWBLK + blockIdx.x] = s;
        g_psq [tid*NROWBLK + blockIdx.x] = q;
    }
}

// ---------------- BN stats ----------------
__global__ void k_bnstat(const float* __restrict__ gamma, const float* __restrict__ beta) {
    int c = blockIdx.x, tid = threadIdx.x;
    __shared__ float s1[256], s2[256];
    float a = 0.f, q = 0.f;
    for (int t = tid; t < NROWBLK; t += 256) { a += g_psum[c*NROWBLK + t]; q += g_psq[c*NROWBLK + t]; }
    s1[tid] = a; s2[tid] = q; __syncthreads();
    for (int s = 128; s > 0; s >>= 1) {
        if (tid < s) { s1[tid] += s1[tid+s]; s2[tid] += s2[tid+s]; }
        __syncthreads();
    }
    if (tid == 0) {
        const float invN = 1.0f / (float)(NB * NL);
        float mu  = s1[0] * invN;
        float var = s2[0] * invN - mu * mu;
        float rs  = rsqrtf(var + 1e-5f);
        float sc  = gamma[c] * rs;
        g_scale[c] = sc;
        g_shift[c] = beta[c] - mu * sc;
    }
}

// ---------------- normalize in place ----------------
__global__ __launch_bounds__(512) void k_norm(float* __restrict__ out) {
    int base = blockIdx.x * 1024 + threadIdx.x;
    #pragma unroll
    for (int r = 0; r < 2; r++) {
        int idx = base + (r << 9);
        float4 v = ((float4*)out)[idx];
        int c = (idx >> 12) & 127;
        float sc = g_scale[c], sh = g_shift[c];
        v.x = fmaf(v.x, sc, sh); v.y = fmaf(v.y, sc, sh);
        v.z = fmaf(v.z, sc, sh); v.w = fmaf(v.w, sc, sh);
        ((float4*)out)[idx] = v;
    }
}

// ---------------- launcher ----------------
extern "C" void kernel_launch(void* const* d_in, const int* in_sizes, int n_in,
                              void* d_out, int out_size) {
    const float* x            = (const float*)d_in[0];
    const float* w_spatial_in = (const float*)d_in[1];
    const float* w_dw_spatial = (const float*)d_in[2];
    const float* w_spatial_out= (const float*)d_in[3];
    const float* w_ch_in      = (const float*)d_in[4];
    const float* w_ch_dw      = (const float*)d_in[5];
    const float* w_ch_out     = (const float*)d_in[6];
    const float* w_mlp1       = (const float*)d_in[7];
    const float* b_mlp1       = (const float*)d_in[8];
    const float* w_mlp2       = (const float*)d_in[9];
    const float* b_mlp2       = (const float*)d_in[10];
    const float* diff_weight  = (const float*)d_in[11];
    const float* bn_gamma     = (const float*)d_in[12];
    const float* bn_beta      = (const float*)d_in[13];
    const float* w_out_proj   = (const float*)d_in[14];
    float* out = (float*)d_out;

    cudaFuncSetAttribute(k_gemm, cudaFuncAttributeMaxDynamicSharedMemorySize, GSMEM);

    k_build<<<NB*NC, 512>>>(x);     // also produces g_gap
    k_prepw<<<NC, 512>>>(w_out_proj, w_spatial_out, w_dw_spatial, w_spatial_in,
                         w_mlp2, b_mlp2, diff_weight);
    k_prep3<<<NB, 1024>>>(w_ch_in, w_ch_dw, w_ch_out, w_mlp1);
    k_vred <<<NB*64, 256>>>(x, b_mlp1);
    k_gemm <<<NROWBLK, 256, GSMEM>>>(x, out);
    k_bnstat<<<NC, 256>>>(bn_gamma, bn_beta);
    k_norm <<<NTOT/4/1024, 512>>>(out);
}

// round 16
// speedup vs baseline: 1.7079x; 1.0141x over previous
#include <cuda_runtime.h>
#include <math.h>
#include <stdint.h>

#define NB 8
#define NC 128
#define NH 128
#define NW 128
#define NL (NH*NW)          // 16384
#define NMID 32
#define KTOT 416
#define NPAN 13
#define NFROWS 288          // nsum(128) + diff(128) + silu(32)
#define NROWBLK 1024
#define NTOT (NB*NC*NL)
#define VT 256              // vred tile positions

// ---------------- device scratch ----------------
__device__ __align__(16) float g_Fg[(size_t)NB*NFROWS*NL];
__device__ float g_gap[NB][NC];
__device__ __align__(16) float g_Bt[KTOT*NC];        // folded weights [k][o]
__device__ __align__(16) float g_Bt2[NPAN*4096];     // mma-fragment order per panel
__device__ float g_ck[NB][3][NC];
__device__ float g_u[NB][NMID];
__device__ float g_b2p[NC];
__device__ float g_psum[NC*NROWBLK];
__device__ float g_psq[NC*NROWBLK];
__device__ float g_scale[NC];
__device__ float g_shift[NC];

// ---------------- helpers ----------------
__device__ __forceinline__ float to_tf32(float x) {
    uint32_t o;
    asm("cvt.rna.tf32.f32 %0, %1;" : "=r"(o) : "f"(x));
    return __uint_as_float(o);
}
__device__ __forceinline__ uint32_t cvt_rna_u(uint32_t x) {
    uint32_t o;
    asm("cvt.rna.tf32.f32 %0, %1;" : "=r"(o) : "f"(__uint_as_float(x)));
    return o;
}
__device__ __forceinline__ void mma_tf32(float* d, const uint32_t* a, const uint32_t* b) {
    asm volatile("mma.sync.aligned.m16n8k8.row.col.f32.tf32.tf32.f32 "
        "{%0,%1,%2,%3}, {%4,%5,%6,%7}, {%8,%9}, {%0,%1,%2,%3};"
        : "+f"(d[0]), "+f"(d[1]), "+f"(d[2]), "+f"(d[3])
        : "r"(a[0]), "r"(a[1]), "r"(a[2]), "r"(a[3]), "r"(b[0]), "r"(b[1]));
}
__device__ __forceinline__ uint32_t smem_u32(const void* p) {
    uint32_t a;
    asm("{ .reg .u64 t; cvta.to.shared.u64 t, %1; cvt.u32.u64 %0, t; }" : "=r"(a) : "l"(p));
    return a;
}
__device__ __forceinline__ void cp16(uint32_t d, const void* s, bool pred) {
    int sz = pred ? 16 : 0;
    asm volatile("cp.async.cg.shared.global [%0], [%1], 16, %2;"
                 :: "r"(d), "l"(s), "r"(sz) : "memory");
}
__device__ __forceinline__ void cp_commit() {
    asm volatile("cp.async.commit_group;" ::: "memory");
}
#define CP_WAIT(n) asm volatile("cp.async.wait_group %0;" :: "n"(n) : "memory")

// ---------------- fold weights — 512 threads, 4-way K split ----------------
__global__ __launch_bounds__(512) void k_prepw(
        const float* __restrict__ wp,  const float* __restrict__ wout,
        const float* __restrict__ wdw, const float* __restrict__ win,
        const float* __restrict__ w2,  const float* __restrict__ b2,
        const float* __restrict__ dwp) {
    const int o = blockIdx.x, tid = threadIdx.x;
    const int c = tid & 127, part = tid >> 7;
    __shared__ float wps[NC], q[NC];
    __shared__ float par[4][NC], parb[4][NC];
    if (tid < NC) wps[tid] = wp[o*NC + tid];
    __syncthreads();
    {
        float a = 0.f;
        const int t0 = part * 32;
        #pragma unroll 8
        for (int j = 0; j < 32; j++) a = fmaf(wps[t0+j], wout[(t0+j)*NC + c], a);
        par[part][c] = a;
    }
    __syncthreads();
    if (tid < NC) q[tid] = (par[0][tid] + par[1][tid]) + (par[2][tid] + par[3][tid]);
    __syncthreads();
    {
        const int t0 = part * 32;
        float a1 = 0.f, a2 = 0.f;
        #pragma unroll 8
        for (int j = 0; j < 32; j++) {
            int s = t0 + j;
            float qs = q[s];
            float w1v = wdw[s*3 + 1], w02 = wdw[s*3 + 0] + wdw[s*3 + 2];
            float wi = win[s*NC + c];
            a1 = fmaf(qs * w1v, wi, a1);
            a2 = fmaf(qs * w02, wi, a2);
        }
        par[part][c] = a1; parb[part][c] = a2;
    }
    __syncthreads();
    if (tid < NC) {
        float A1 = (par[0][tid] + par[1][tid]) + (par[2][tid] + par[3][tid]) + wps[tid];
        float A2 = 0.25f * ((parb[0][tid] + parb[1][tid]) + (parb[2][tid] + parb[3][tid]));
        g_Bt[tid*NC + o]          = to_tf32(A1);
        g_Bt[(NC + tid)*NC + o]   = to_tf32(A2);
        g_Bt[(2*NC + tid)*NC + o] = to_tf32(dwp[0] * wps[tid]);
    }
    __syncthreads();
    if (tid < NC) {
        int m = tid & 31, p4 = tid >> 5;
        float s4 = 0.f;
        const int t0 = p4 * 32;
        #pragma unroll 8
        for (int j = 0; j < 32; j++) s4 = fmaf(wps[t0+j], w2[(t0+j)*NMID + m], s4);
        par[p4][m] = s4;
        parb[0][tid] = wps[tid] * b2[tid];
    }
    __syncthreads();
    if (tid < 32) {
        g_Bt[(3*NC + tid)*NC + o] =
            to_tf32((par[0][tid] + par[1][tid]) + (par[2][tid] + par[3][tid]));
        float s = (parb[0][tid] + parb[0][tid+32]) + (parb[0][tid+64] + parb[0][tid+96]);
        for (int ofs = 16; ofs; ofs >>= 1) s += __shfl_xor_sync(0xffffffff, s, ofs);
        if (tid == 0) g_b2p[o] = s;
    }
}

// ---------------- repack g_Bt into per-panel mma-fragment order ----------------
// g_Bt2[p*4096 + (((mt*8 + ks*2 + m2)*32 + lane)*4 + j)]
//   j=0:(k0,o0) j=1:(k0,o0+8) j=2:(k0+4,o0) j=3:(k0+4,o0+8)
//   k0 = p*32 + ks*8 + tg, o0 = m2*64 + mt*16 + g  (g=lane>>2, tg=lane&3)
__global__ void k_repack() {
    const int p = blockIdx.x;
    for (int idx = threadIdx.x; idx < 4096; idx += 256) {
        int j = idx & 3, lane = (idx >> 2) & 31, rest = idx >> 7;
        int m2 = rest & 1, ks = (rest >> 1) & 3, mt = rest >> 3;
        int g = lane >> 2, tg = lane & 3;
        int k = p*32 + ks*8 + tg + ((j >> 1) ? 4 : 0);
        int o = m2*64 + mt*16 + g + ((j & 1) ? 8 : 0);
        g_Bt2[p*4096 + idx] = g_Bt[k*NC + o];
    }
}

// ---------------- per-batch vectors — 1024 threads, 8-way K split ----------------
__global__ __launch_bounds__(1024) void k_prep3(
        const float* __restrict__ wci, const float* __restrict__ wdwch,
        const float* __restrict__ wco, const float* __restrict__ w1) {
    const int b = blockIdx.x, tid = threadIdx.x;
    const int c = tid & 127, part = tid >> 7;
    __shared__ float gs[NC], g2s[NC];
    __shared__ float par[8][NC];
    __shared__ float par3[3][8][NC];
    __shared__ float nrm_s;
    if (tid < NC) { float g = g_gap[b][tid]; par[0][tid] = g * g; }
    __syncthreads();
    if (tid < 32) {
        float s = (par[0][tid] + par[0][tid+32]) + (par[0][tid+64] + par[0][tid+96]);
        for (int o = 16; o; o >>= 1) s += __shfl_xor_sync(0xffffffff, s, o);
        if (tid == 0) nrm_s = fmaxf(sqrtf(s), 1e-12f);
    }
    __syncthreads();
    if (tid < NC) gs[tid] = g_gap[b][tid] / nrm_s;
    __syncthreads();
    {
        float a = 0.f;
        const int t0 = part * 16;
        #pragma unroll
        for (int j = 0; j < 16; j++) a = fmaf(gs[t0+j], wco[(t0+j)*NC + c], a);
        par[part][c] = a;
    }
    __syncthreads();
    if (tid < NC) {
        float a = 0.f;
        #pragma unroll
        for (int p = 0; p < 8; p++) a += par[p][tid];
        g2s[tid] = a;
    }
    __syncthreads();
    {
        const int t0 = part * 16;
        float s0 = 0.f, s1 = 0.f, s2 = 0.f;
        #pragma unroll
        for (int j = 0; j < 16; j++) {
            int t = t0 + j;
            float wv = wci[t*NC + c] * g2s[t];
            s0 = fmaf(wv, wdwch[t*3 + 0], s0);
            s1 = fmaf(wv, wdwch[t*3 + 1], s1);
            s2 = fmaf(wv, wdwch[t*3 + 2], s2);
        }
        par3[0][part][c] = s0; par3[1][part][c] = s1; par3[2][part][c] = s2;
    }
    __syncthreads();
    if (tid < 384) {
        int k = tid >> 7, cc = tid & 127;
        float a = 0.f;
        #pragma unroll
        for (int p = 0; p < 8; p++) a += par3[k][p][cc];
        g_ck[b][k][cc] = a;
    }
    {
        int m = tid & 31, pt = tid >> 5;
        const int t0 = pt * 4;
        float s = 0.f;
        #pragma unroll
        for (int j = 0; j < 4; j++) s = fmaf(w1[m*NC + t0+j], gs[t0+j], s);
        ((float*)par)[pt*32 + m] = s;
    }
    __syncthreads();
    if (tid < NMID) {
        float s = 0.f;
        #pragma unroll
        for (int p = 0; p < 32; p++) s += ((float*)par)[p*32 + tid];
        g_u[b][tid] = s;
    }
}

// ---------------- stencil build + fused gap ----------------
__global__ __launch_bounds__(512) void k_build(const float* __restrict__ x) {
    __shared__ float red[512];
    const int bx = blockIdx.x;
    const int b = bx >> 7, c = bx & 127;
    const float* xp = x + (size_t)(b*NC + c) * NL;
    float* nrow = g_Fg + (size_t)b*NFROWS*NL + (size_t)c*NL;
    float* drow = nrow + (size_t)NC*NL;
    const int tid = threadIdx.x;
    float gsum = 0.f;
    #pragma unroll 2
    for (int r = 0; r < 8; r++) {
        int p4 = tid + (r << 9);
        int pos = p4 << 2;
        int i = pos >> 7, j0 = pos & 127;
        float4 c4 = ((const float4*)xp)[p4];
        gsum += (c4.x + c4.y) + (c4.z + c4.w);
        float lprev = (pos > 0) ? xp[pos-1] : 0.f;
        float rnext = (pos < NL-4) ? xp[pos+4] : 0.f;
        float u0,u1,u2,u3, d0,d1,d2,d3;
        if (i > 0) {
            float4 up4 = ((const float4*)xp)[p4-32];
            u0 = up4.x; u1 = up4.y; u2 = up4.z; u3 = up4.w;
        } else {
            u0 = (j0 > 0) ? xp[127*NW + j0-1] : 0.f;
            u1 = xp[127*NW + j0];
            u2 = xp[127*NW + j0+1];
            u3 = xp[127*NW + j0+2];
        }
        if (i < 127) {
            float4 dn4 = ((const float4*)xp)[p4+32];
            d0 = dn4.x; d1 = dn4.y; d2 = dn4.z; d3 = dn4.w;
        } else {
            d0 = xp[j0+1]; d1 = xp[j0+2]; d2 = xp[j0+3];
            d3 = (j0+3 < 127) ? xp[j0+4] : 0.f;
        }
        float l0 = lprev, l1 = c4.x, l2 = c4.y, l3 = c4.z;
        float r0 = c4.y, r1 = c4.z, r2 = c4.w, r3 = rnext;
        ((float4*)nrow)[p4] = make_float4(to_tf32((l0+r0)+(u0+d0)), to_tf32((l1+r1)+(u1+d1)),
                                          to_tf32((l2+r2)+(u2+d2)), to_tf32((l3+r3)+(u3+d3)));
        float lr0 = (j0 == 0) ? c4.y : lprev;
        float rr3 = (j0 == 124) ? c4.z : rnext;
        float ur0,ur1,ur2,ur3, dr0,dr1,dr2,dr3;
        if (i > 0) { ur0=u0; ur1=u1; ur2=u2; ur3=u3; }
        else       { ur0=d0; ur1=d1; ur2=d2; ur3=d3; }
        if (i < 127) { dr0=d0; dr1=d1; dr2=d2; dr3=d3; }
        else         { dr0=u0; dr1=u1; dr2=u2; dr3=u3; }
        float df0 = 0.25f*((fabsf(c4.x-lr0)+fabsf(c4.x-c4.y))+(fabsf(c4.x-ur0)+fabsf(c4.x-dr0)));
        float df1 = 0.25f*((fabsf(c4.y-c4.x)+fabsf(c4.y-c4.z))+(fabsf(c4.y-ur1)+fabsf(c4.y-dr1)));
        float df2 = 0.25f*((fabsf(c4.z-c4.y)+fabsf(c4.z-c4.w))+(fabsf(c4.z-ur2)+fabsf(c4.z-dr2)));
        float df3 = 0.25f*((fabsf(c4.w-c4.z)+fabsf(c4.w-rr3))+(fabsf(c4.w-ur3)+fabsf(c4.w-dr3)));
        ((float4*)drow)[p4] = make_float4(to_tf32(df0), to_tf32(df1), to_tf32(df2), to_tf32(df3));
    }
    red[tid] = gsum;
    __syncthreads();
    for (int k = 256; k > 0; k >>= 1) {
        if (tid < k) red[tid] += red[tid + k];
        __syncthreads();
    }
    if (tid == 0) g_gap[b][c] = red[0] * (1.0f / NL);
}

// ---------------- v reduction + silu: 512 blocks x 256 thr, 4-way channel split ----------------
__global__ __launch_bounds__(256) void k_vred(const float* __restrict__ x,
                                              const float* __restrict__ b1) {
    __shared__ float4 P0[4][64], P1[4][64], P2[4][64];
    __shared__ float s0f[VT+1], s1f[VT], s2f[VT+1];
    __shared__ float cks[3*NC], us[NMID], b1s[NMID];
    __shared__ float hLs[4], hRs[4];
    const int tid = threadIdx.x;
    const int b = blockIdx.x >> 6;
    const int tb = (blockIdx.x & 63) << 8;
    const int q = tid & 63, part = tid >> 6;
    const float* xb = x + (size_t)b * NC * NL;

    for (int t = tid; t < 3*NC; t += 256) cks[t] = (&g_ck[b][0][0])[t];
    if (tid < NMID) { us[tid] = g_u[b][tid]; b1s[tid] = b1[tid]; }
    __syncthreads();

    const int cb = part << 5;
    const float* base = xb + (size_t)cb * NL + tb;
    const bool hL = (q == 0)  && (tb > 0);
    const bool hR = (q == 63) && (tb + VT < NL);
    float a0x=0,a0y=0,a0z=0,a0w=0, a1x=0,a1y=0,a1z=0,a1w=0, a2x=0,a2y=0,a2z=0,a2w=0;
    float h = 0.f;
    #pragma unroll 8
    for (int c = 0; c < 32; c++) {
        float4 xv = ((const float4*)(base + (size_t)c * NL))[q];
        float k0 = cks[cb + c], k1 = cks[NC + cb + c], k2 = cks[2*NC + cb + c];
        a0x = fmaf(k0, xv.x, a0x); a0y = fmaf(k0, xv.y, a0y);
        a0z = fmaf(k0, xv.z, a0z); a0w = fmaf(k0, xv.w, a0w);
        a1x = fmaf(k1, xv.x, a1x); a1y = fmaf(k1, xv.y, a1y);
        a1z = fmaf(k1, xv.z, a1z); a1w = fmaf(k1, xv.w, a1w);
        a2x = fmaf(k2, xv.x, a2x); a2y = fmaf(k2, xv.y, a2y);
        a2z = fmaf(k2, xv.z, a2z); a2w = fmaf(k2, xv.w, a2w);
        if (hL) h = fmaf(k0, base[(size_t)c*NL - 1], h);
        if (hR) h = fmaf(k2, base[(size_t)c*NL + VT], h);
    }
    P0[part][q] = make_float4(a0x, a0y, a0z, a0w);
    P1[part][q] = make_float4(a1x, a1y, a1z, a1w);
    P2[part][q] = make_float4(a2x, a2y, a2z, a2w);
    if (q == 0)  hLs[part] = hL ? h : 0.f;
    if (q == 63) hRs[part] = hR ? h : 0.f;
    __syncthreads();
    if (tid < 64) {
        float4 t0 = P0[0][tid], t1 = P0[1][tid], t2 = P0[2][tid], t3 = P0[3][tid];
        float4 u0 = P1[0][tid], u1 = P1[1][tid], u2 = P1[2][tid], u3 = P1[3][tid];
        float4 w0 = P2[0][tid], w1 = P2[1][tid], w2 = P2[2][tid], w3 = P2[3][tid];
        int i0 = tid << 2;
        s0f[i0+1] = (t0.x+t1.x)+(t2.x+t3.x); s0f[i0+2] = (t0.y+t1.y)+(t2.y+t3.y);
        s0f[i0+3] = (t0.z+t1.z)+(t2.z+t3.z); s0f[i0+4] = (t0.w+t1.w)+(t2.w+t3.w);
        s1f[i0]   = (u0.x+u1.x)+(u2.x+u3.x); s1f[i0+1] = (u0.y+u1.y)+(u2.y+u3.y);
        s1f[i0+2] = (u0.z+u1.z)+(u2.z+u3.z); s1f[i0+3] = (u0.w+u1.w)+(u2.w+u3.w);
        s2f[i0]   = (w0.x+w1.x)+(w2.x+w3.x); s2f[i0+1] = (w0.y+w1.y)+(w2.y+w3.y);
        s2f[i0+2] = (w0.z+w1.z)+(w2.z+w3.z); s2f[i0+3] = (w0.w+w1.w)+(w2.w+w3.w);
        if (tid == 0)  s0f[0]  = (hLs[0]+hLs[1])+(hLs[2]+hLs[3]);
        if (tid == 63) s2f[VT] = (hRs[0]+hRs[1])+(hRs[2]+hRs[3]);
    }
    __syncthreads();
    {
        int i0 = q << 2;
        float v0 = s0f[i0]   + s1f[i0]   + s2f[i0+1];
        float v1 = s0f[i0+1] + s1f[i0+1] + s2f[i0+2];
        float v2 = s0f[i0+2] + s1f[i0+2] + s2f[i0+3];
        float v3 = s0f[i0+3] + s1f[i0+3] + s2f[i0+4];
        float* dst = g_Fg + (size_t)b*NFROWS*NL + (size_t)(2*NC)*NL + tb + i0;
        const int m0 = part << 3;
        #pragma unroll 4
        for (int m = m0; m < m0 + 8; m++) {
            float um = us[m], bm = b1s[m];
            float z0 = fmaf(um, v0, bm), z1 = fmaf(um, v1, bm);
            float z2 = fmaf(um, v2, bm), z3 = fmaf(um, v3, bm);
            *(float4*)(dst + (size_t)m * NL) = make_float4(
                to_tf32(z0 / (1.f + __expf(-z0))), to_tf32(z1 / (1.f + __expf(-z1))),
                to_tf32(z2 / (1.f + __expf(-z2))), to_tf32(z3 / (1.f + __expf(-z3))));
        }
    }
}

// ---------------- streaming GEMM with fragment-order A, writes pre-BN to out ----------------
#define GSMEM (3*8192*4)

__global__ __launch_bounds__(256, 2) void k_gemm(const float* __restrict__ x,
                                                 float* __restrict__ out) {
    extern __shared__ __align__(16) float sm[];
    const int tid = threadIdx.x;
    const int b = blockIdx.x >> 7;
    const int posb = (blockIdx.x & 127) << 7;
    const float* xb  = x + (size_t)b * NC * NL + posb;
    const float* fgb = g_Fg + (size_t)b * NFROWS * NL + posb;

    auto issueP = [&](int p, int st) {
        int k0 = p * 32;
        const float* bsrc = (k0 < NC) ? (xb + (size_t)k0 * NL) : (fgb + (size_t)(k0 - NC) * NL);
        const float* asrc = g_Bt2 + p * 4096;
        uint32_t ab = smem_u32(sm + st * 8192);
        uint32_t bb = ab + 16384;
        #pragma unroll
        for (int r = 0; r < 4; r++) {
            int f = tid + (r << 8);
            // A: linear fragment-order copy
            cp16(ab + f*16, asrc + f*4, true);
            // B: swizzled
            int kr = f >> 5, j4 = f & 31;
            int sw = (kr*32 + (j4 ^ ((kr & 3) << 1))) * 16;
            cp16(bb + sw, bsrc + (size_t)kr*NL + (j4 << 2), true);
        }
        cp_commit();
    };
    issueP(0, 0); issueP(1, 1);

    const int lane = tid & 31, g = lane >> 2, tg = lane & 3;
    const int w = tid >> 5, m2 = w >> 2, mbase = m2 * 64, nbase = (w & 3) * 32;
    const int swa = tg << 3;
    float dacc[4][4][4];
    #pragma unroll
    for (int mt = 0; mt < 4; mt++)
        #pragma unroll
        for (int nt = 0; nt < 4; nt++)
            #pragma unroll
            for (int qq = 0; qq < 4; qq++) dacc[mt][nt][qq] = 0.f;

    auto mmaPanel = [&](const float* As, bool cvt) {
        const uint32_t* Fu = (const uint32_t*)As + 4096;
        #pragma unroll
        for (int ks = 0; ks < 4; ks++) {
            const int kr = ks * 8;
            float4 afv[4];
            #pragma unroll
            for (int mt = 0; mt < 4; mt++)
                afv[mt] = *(const float4*)(As + (((mt*8 + ks*2 + m2)*32 + lane) << 2));
            uint32_t bf[4][2];
            #pragma unroll
            for (int nt = 0; nt < 4; nt++) {
                int n = nbase + nt*8 + g;
                uint32_t v0 = Fu[(kr + tg)*128 + (n ^ swa)];
                uint32_t v1 = Fu[(kr + tg + 4)*128 + (n ^ swa)];
                bf[nt][0] = cvt ? cvt_rna_u(v0) : v0;
                bf[nt][1] = cvt ? cvt_rna_u(v1) : v1;
            }
            #pragma unroll
            for (int mt = 0; mt < 4; mt++) {
                uint32_t af[4] = { __float_as_uint(afv[mt].x), __float_as_uint(afv[mt].y),
                                   __float_as_uint(afv[mt].z), __float_as_uint(afv[mt].w) };
                #pragma unroll
                for (int nt = 0; nt < 4; nt++)
                    mma_tf32(dacc[mt][nt], af, bf[nt]);
            }
        }
    };

    int st = 0;
    #pragma unroll 1
    for (int p = 0; p < NPAN; p++) {
        if (p < NPAN-1) { CP_WAIT(1); } else { CP_WAIT(0); }
        __syncthreads();
        if (p + 2 < NPAN) issueP(p + 2, (p + 2) % 3);
        mmaPanel(sm + st * 8192, p < 4);
        st = (st == 2) ? 0 : st + 1;
    }
    __syncthreads();

    // ---- epilogue: bias, pre-BN store to out, BN partials ----
    float* sred = sm;
    #pragma unroll
    for (int mt = 0; mt < 4; mt++) {
        int o0 = mbase + mt*16 + g, o1 = o0 + 8;
        float bb0 = g_b2p[o0], bb1 = g_b2p[o1];
        float* row0 = &out[(size_t)(b*NC + o0) * NL + posb];
        float* row1 = &out[(size_t)(b*NC + o1) * NL + posb];
        float s0 = 0.f, q0 = 0.f, s1 = 0.f, q1 = 0.f;
        #pragma unroll
        for (int nt = 0; nt < 4; nt++) {
            float v0 = dacc[mt][nt][0] + bb0, v1 = dacc[mt][nt][1] + bb0;
            float v2 = dacc[mt][nt][2] + bb1, v3 = dacc[mt][nt][3] + bb1;
            int j = nbase + nt*8 + 2*tg;
            *(float2*)(row0 + j) = make_float2(v0, v1);
            *(float2*)(row1 + j) = make_float2(v2, v3);
            s0 += v0 + v1; q0 = fmaf(v0, v0, q0); q0 = fmaf(v1, v1, q0);
            s1 += v2 + v3; q1 = fmaf(v2, v2, q1); q1 = fmaf(v3, v3, q1);
        }
        s0 += __shfl_xor_sync(0xffffffff, s0, 1); s0 += __shfl_xor_sync(0xffffffff, s0, 2);
        q0 += __shfl_xor_sync(0xffffffff, q0, 1); q0 += __shfl_xor_sync(0xffffffff, q0, 2);
        s1 += __shfl_xor_sync(0xffffffff, s1, 1); s1 += __shfl_xor_sync(0xffffffff, s1, 2);
        q1 += __shfl_xor_sync(0xffffffff, q1, 1); q1 += __shfl_xor_sync(0xffffffff, q1, 2);
        if (tg == 0) {
            int nwq = w & 3;
            sred[o0*4 + nwq] = s0; sred[512 + o0*4 + nwq] = q0;
            sred[o1*4 + nwq] = s1; sred[512 + o1*4 + nwq] = q1;
        }
    }
    __syncthreads();
    if (tid < NC) {
        float s = 0.f, q = 0.f;
        #pragma unroll
        for (int t = 0; t < 4; t++) { s += sred[tid*4 + t]; q += sred[512 + tid*4 + t]; }
        g_psum[tid*NROWBLK + blockIdx.x] = s;
        g_psq [tid*NROWBLK + blockIdx.x] = q;
    }
}

// ---------------- BN stats ----------------
__global__ void k_bnstat(const float* __restrict__ gamma, const float* __restrict__ beta) {
    int c = blockIdx.x, tid = threadIdx.x;
    __shared__ float s1[256], s2[256];
    float a = 0.f, q = 0.f;
    for (int t = tid; t < NROWBLK; t += 256) { a += g_psum[c*NROWBLK + t]; q += g_psq[c*NROWBLK + t]; }
    s1[tid] = a; s2[tid] = q; __syncthreads();
    for (int s = 128; s > 0; s >>= 1) {
        if (tid < s) { s1[tid] += s1[tid+s]; s2[tid] += s2[tid+s]; }
        __syncthreads();
    }
    if (tid == 0) {
        const float invN = 1.0f / (float)(NB * NL);
        float mu  = s1[0] * invN;
        float var = s2[0] * invN - mu * mu;
        float rs  = rsqrtf(var + 1e-5f);
        float sc  = gamma[c] * rs;
        g_scale[c] = sc;
        g_shift[c] = beta[c] - mu * sc;
    }
}

// ---------------- normalize in place ----------------
__global__ __launch_bounds__(512) void k_norm(float* __restrict__ out) {
    int base = blockIdx.x * 1024 + threadIdx.x;
    #pragma unroll
    for (int r = 0; r < 2; r++) {
        int idx = base + (r << 9);
        float4 v = ((float4*)out)[idx];
        int c = (idx >> 12) & 127;
        float sc = g_scale[c], sh = g_shift[c];
        v.x = fmaf(v.x, sc, sh); v.y = fmaf(v.y, sc, sh);
        v.z = fmaf(v.z, sc, sh); v.w = fmaf(v.w, sc, sh);
        ((float4*)out)[idx] = v;
    }
}

// ---------------- launcher ----------------
extern "C" void kernel_launch(void* const* d_in, const int* in_sizes, int n_in,
                              void* d_out, int out_size) {
    const float* x            = (const float*)d_in[0];
    const float* w_spatial_in = (const float*)d_in[1];
    const float* w_dw_spatial = (const float*)d_in[2];
    const float* w_spatial_out= (const float*)d_in[3];
    const float* w_ch_in      = (const float*)d_in[4];
    const float* w_ch_dw      = (const float*)d_in[5];
    const float* w_ch_out     = (const float*)d_in[6];
    const float* w_mlp1       = (const float*)d_in[7];
    const float* b_mlp1       = (const float*)d_in[8];
    const float* w_mlp2       = (const float*)d_in[9];
    const float* b_mlp2       = (const float*)d_in[10];
    const float* diff_weight  = (const float*)d_in[11];
    const float* bn_gamma     = (const float*)d_in[12];
    const float* bn_beta      = (const float*)d_in[13];
    const float* w_out_proj   = (const float*)d_in[14];
    float* out = (float*)d_out;

    cudaFuncSetAttribute(k_gemm, cudaFuncAttributeMaxDynamicSharedMemorySize, GSMEM);

    k_build<<<NB*NC, 512>>>(x);     // also produces g_gap
    k_prepw<<<NC, 512>>>(w_out_proj, w_spatial_out, w_dw_spatial, w_spatial_in,
                         w_mlp2, b_mlp2, diff_weight);
    k_repack<<<NPAN, 256>>>();
    k_prep3<<<NB, 1024>>>(w_ch_in, w_ch_dw, w_ch_out, w_mlp1);
    k_vred <<<NB*64, 256>>>(x, b_mlp1);
    k_gemm <<<NROWBLK, 256, GSMEM>>>(x, out);
    k_bnstat<<<NC, 256>>>(bn_gamma, bn_beta);
    k_norm <<<NTOT/4/1024, 512>>>(out);
}

// round 17
// speedup vs baseline: 1.7238x; 1.0093x over previous
#include <cuda_runtime.h>
#include <math.h>
#include <stdint.h>

#define NB 8
#define NC 128
#define NH 128
#define NW 128
#define NL (NH*NW)          // 16384
#define NMID 32
#define KTOT 416
#define NPAN 13
#define NFROWS 288          // nsum(128) + diff(128) + silu(32)
#define NROWBLK 1024
#define NTOT (NB*NC*NL)
#define VT 256              // vred tile positions

// ---------------- device scratch ----------------
__device__ __align__(16) float g_Fg[(size_t)NB*NFROWS*NL];
__device__ float g_gap[NB][NC];
__device__ __align__(16) float g_Bt2[NPAN*4096];     // folded weights, mma-fragment order
__device__ float g_ck[NB][3][NC];
__device__ float g_u[NB][NMID];
__device__ float g_b2p[NC];
__device__ float g_psum[NC*NROWBLK];
__device__ float g_psq[NC*NROWBLK];
__device__ float g_scale[NC];
__device__ float g_shift[NC];

// ---------------- helpers ----------------
__device__ __forceinline__ float to_tf32(float x) {
    uint32_t o;
    asm("cvt.rna.tf32.f32 %0, %1;" : "=r"(o) : "f"(x));
    return __uint_as_float(o);
}
__device__ __forceinline__ uint32_t cvt_rna_u(uint32_t x) {
    uint32_t o;
    asm("cvt.rna.tf32.f32 %0, %1;" : "=r"(o) : "f"(__uint_as_float(x)));
    return o;
}
__device__ __forceinline__ void mma_tf32(float* d, const uint32_t* a, const uint32_t* b) {
    asm volatile("mma.sync.aligned.m16n8k8.row.col.f32.tf32.tf32.f32 "
        "{%0,%1,%2,%3}, {%4,%5,%6,%7}, {%8,%9}, {%0,%1,%2,%3};"
        : "+f"(d[0]), "+f"(d[1]), "+f"(d[2]), "+f"(d[3])
        : "r"(a[0]), "r"(a[1]), "r"(a[2]), "r"(a[3]), "r"(b[0]), "r"(b[1]));
}
__device__ __forceinline__ uint32_t smem_u32(const void* p) {
    uint32_t a;
    asm("{ .reg .u64 t; cvta.to.shared.u64 t, %1; cvt.u32.u64 %0, t; }" : "=r"(a) : "l"(p));
    return a;
}
__device__ __forceinline__ void cp16(uint32_t d, const void* s, bool pred) {
    int sz = pred ? 16 : 0;
    asm volatile("cp.async.cg.shared.global [%0], [%1], 16, %2;"
                 :: "r"(d), "l"(s), "r"(sz) : "memory");
}
__device__ __forceinline__ void cp_commit() {
    asm volatile("cp.async.commit_group;" ::: "memory");
}
#define CP_WAIT(n) asm volatile("cp.async.wait_group %0;" :: "n"(n) : "memory")

// fragment index for folded weight element (k, o):
//   k0 = p*32 + ks*8 + tg (+4 if khi), o0 = m2*64 + mt*16 + g (+8 if j0)
//   idx = p*4096 + (((mt*8 + ks*2 + m2)*32 + g*4+tg)<<2) + ((khi<<1)|j0)
__device__ __forceinline__ int frag_idx(int k, int o) {
    int p = k >> 5, kk = k & 31;
    int ks = kk >> 3, t7 = kk & 7, tg = t7 & 3, khi = t7 >> 2;
    int m2 = o >> 6, oo = o & 63, mt = oo >> 4, r = oo & 15;
    int j0 = r >> 3, g = r & 7;
    return p*4096 + ((((mt*8 + ks*2 + m2)*32 + g*4 + tg) << 2) | ((khi << 1) | j0));
}

// ---------------- fold weights -> g_Bt2 (fragment order) — 512 threads ----------------
__global__ __launch_bounds__(512) void k_prepw(
        const float* __restrict__ wp,  const float* __restrict__ wout,
        const float* __restrict__ wdw, const float* __restrict__ win,
        const float* __restrict__ w2,  const float* __restrict__ b2,
        const float* __restrict__ dwp) {
    const int o = blockIdx.x, tid = threadIdx.x;
    const int c = tid & 127, part = tid >> 7;
    __shared__ float wps[NC], q[NC];
    __shared__ float par[4][NC], parb[4][NC];
    if (tid < NC) wps[tid] = wp[o*NC + tid];
    __syncthreads();
    {
        float a = 0.f;
        const int t0 = part * 32;
        #pragma unroll 8
        for (int j = 0; j < 32; j++) a = fmaf(wps[t0+j], wout[(t0+j)*NC + c], a);
        par[part][c] = a;
    }
    __syncthreads();
    if (tid < NC) q[tid] = (par[0][tid] + par[1][tid]) + (par[2][tid] + par[3][tid]);
    __syncthreads();
    {
        const int t0 = part * 32;
        float a1 = 0.f, a2 = 0.f;
        #pragma unroll 8
        for (int j = 0; j < 32; j++) {
            int s = t0 + j;
            float qs = q[s];
            float w1v = wdw[s*3 + 1], w02 = wdw[s*3 + 0] + wdw[s*3 + 2];
            float wi = win[s*NC + c];
            a1 = fmaf(qs * w1v, wi, a1);
            a2 = fmaf(qs * w02, wi, a2);
        }
        par[part][c] = a1; parb[part][c] = a2;
    }
    __syncthreads();
    if (tid < NC) {
        float A1 = (par[0][tid] + par[1][tid]) + (par[2][tid] + par[3][tid]) + wps[tid];
        float A2 = 0.25f * ((parb[0][tid] + parb[1][tid]) + (parb[2][tid] + parb[3][tid]));
        g_Bt2[frag_idx(tid, o)]        = to_tf32(A1);            // k 0..127
        g_Bt2[frag_idx(NC + tid, o)]   = to_tf32(A2);            // k 128..255
        g_Bt2[frag_idx(2*NC + tid, o)] = to_tf32(dwp[0] * wps[tid]); // k 256..383
    }
    __syncthreads();
    if (tid < NC) {
        int m = tid & 31, p4 = tid >> 5;
        float s4 = 0.f;
        const int t0 = p4 * 32;
        #pragma unroll 8
        for (int j = 0; j < 32; j++) s4 = fmaf(wps[t0+j], w2[(t0+j)*NMID + m], s4);
        par[p4][m] = s4;
        parb[0][tid] = wps[tid] * b2[tid];
    }
    __syncthreads();
    if (tid < 32) {
        g_Bt2[frag_idx(3*NC + tid, o)] =
            to_tf32((par[0][tid] + par[1][tid]) + (par[2][tid] + par[3][tid]));
        float s = (parb[0][tid] + parb[0][tid+32]) + (parb[0][tid+64] + parb[0][tid+96]);
        for (int ofs = 16; ofs; ofs >>= 1) s += __shfl_xor_sync(0xffffffff, s, ofs);
        if (tid == 0) g_b2p[o] = s;
    }
}

// ---------------- per-batch vectors — 1024 threads, 8-way K split ----------------
__global__ __launch_bounds__(1024) void k_prep3(
        const float* __restrict__ wci, const float* __restrict__ wdwch,
        const float* __restrict__ wco, const float* __restrict__ w1) {
    const int b = blockIdx.x, tid = threadIdx.x;
    const int c = tid & 127, part = tid >> 7;
    __shared__ float gs[NC], g2s[NC];
    __shared__ float par[8][NC];
    __shared__ float par3[3][8][NC];
    __shared__ float nrm_s;
    if (tid < NC) { float g = g_gap[b][tid]; par[0][tid] = g * g; }
    __syncthreads();
    if (tid < 32) {
        float s = (par[0][tid] + par[0][tid+32]) + (par[0][tid+64] + par[0][tid+96]);
        for (int o = 16; o; o >>= 1) s += __shfl_xor_sync(0xffffffff, s, o);
        if (tid == 0) nrm_s = fmaxf(sqrtf(s), 1e-12f);
    }
    __syncthreads();
    if (tid < NC) gs[tid] = g_gap[b][tid] / nrm_s;
    __syncthreads();
    {
        float a = 0.f;
        const int t0 = part * 16;
        #pragma unroll
        for (int j = 0; j < 16; j++) a = fmaf(gs[t0+j], wco[(t0+j)*NC + c], a);
        par[part][c] = a;
    }
    __syncthreads();
    if (tid < NC) {
        float a = 0.f;
        #pragma unroll
        for (int p = 0; p < 8; p++) a += par[p][tid];
        g2s[tid] = a;
    }
    __syncthreads();
    {
        const int t0 = part * 16;
        float s0 = 0.f, s1 = 0.f, s2 = 0.f;
        #pragma unroll
        for (int j = 0; j < 16; j++) {
            int t = t0 + j;
            float wv = wci[t*NC + c] * g2s[t];
            s0 = fmaf(wv, wdwch[t*3 + 0], s0);
            s1 = fmaf(wv, wdwch[t*3 + 1], s1);
            s2 = fmaf(wv, wdwch[t*3 + 2], s2);
        }
        par3[0][part][c] = s0; par3[1][part][c] = s1; par3[2][part][c] = s2;
    }
    __syncthreads();
    if (tid < 384) {
        int k = tid >> 7, cc = tid & 127;
        float a = 0.f;
        #pragma unroll
        for (int p = 0; p < 8; p++) a += par3[k][p][cc];
        g_ck[b][k][cc] = a;
    }
    {
        int m = tid & 31, pt = tid >> 5;
        const int t0 = pt * 4;
        float s = 0.f;
        #pragma unroll
        for (int j = 0; j < 4; j++) s = fmaf(w1[m*NC + t0+j], gs[t0+j], s);
        ((float*)par)[pt*32 + m] = s;
    }
    __syncthreads();
    if (tid < NMID) {
        float s = 0.f;
        #pragma unroll
        for (int p = 0; p < 32; p++) s += ((float*)par)[p*32 + tid];
        g_u[b][tid] = s;
    }
}

// ---------------- stencil build + fused gap ----------------
__global__ __launch_bounds__(512) void k_build(const float* __restrict__ x) {
    __shared__ float red[512];
    const int bx = blockIdx.x;
    const int b = bx >> 7, c = bx & 127;
    const float* xp = x + (size_t)(b*NC + c) * NL;
    float* nrow = g_Fg + (size_t)b*NFROWS*NL + (size_t)c*NL;
    float* drow = nrow + (size_t)NC*NL;
    const int tid = threadIdx.x;
    float gsum = 0.f;
    #pragma unroll 2
    for (int r = 0; r < 8; r++) {
        int p4 = tid + (r << 9);
        int pos = p4 << 2;
        int i = pos >> 7, j0 = pos & 127;
        float4 c4 = ((const float4*)xp)[p4];
        gsum += (c4.x + c4.y) + (c4.z + c4.w);
        float lprev = (pos > 0) ? xp[pos-1] : 0.f;
        float rnext = (pos < NL-4) ? xp[pos+4] : 0.f;
        float u0,u1,u2,u3, d0,d1,d2,d3;
        if (i > 0) {
            float4 up4 = ((const float4*)xp)[p4-32];
            u0 = up4.x; u1 = up4.y; u2 = up4.z; u3 = up4.w;
        } else {
            u0 = (j0 > 0) ? xp[127*NW + j0-1] : 0.f;
            u1 = xp[127*NW + j0];
            u2 = xp[127*NW + j0+1];
            u3 = xp[127*NW + j0+2];
        }
        if (i < 127) {
            float4 dn4 = ((const float4*)xp)[p4+32];
            d0 = dn4.x; d1 = dn4.y; d2 = dn4.z; d3 = dn4.w;
        } else {
            d0 = xp[j0+1]; d1 = xp[j0+2]; d2 = xp[j0+3];
            d3 = (j0+3 < 127) ? xp[j0+4] : 0.f;
        }
        float l0 = lprev, l1 = c4.x, l2 = c4.y, l3 = c4.z;
        float r0 = c4.y, r1 = c4.z, r2 = c4.w, r3 = rnext;
        ((float4*)nrow)[p4] = make_float4(to_tf32((l0+r0)+(u0+d0)), to_tf32((l1+r1)+(u1+d1)),
                                          to_tf32((l2+r2)+(u2+d2)), to_tf32((l3+r3)+(u3+d3)));
        float lr0 = (j0 == 0) ? c4.y : lprev;
        float rr3 = (j0 == 124) ? c4.z : rnext;
        float ur0,ur1,ur2,ur3, dr0,dr1,dr2,dr3;
        if (i > 0) { ur0=u0; ur1=u1; ur2=u2; ur3=u3; }
        else       { ur0=d0; ur1=d1; ur2=d2; ur3=d3; }
        if (i < 127) { dr0=d0; dr1=d1; dr2=d2; dr3=d3; }
        else         { dr0=u0; dr1=u1; dr2=u2; dr3=u3; }
        float df0 = 0.25f*((fabsf(c4.x-lr0)+fabsf(c4.x-c4.y))+(fabsf(c4.x-ur0)+fabsf(c4.x-dr0)));
        float df1 = 0.25f*((fabsf(c4.y-c4.x)+fabsf(c4.y-c4.z))+(fabsf(c4.y-ur1)+fabsf(c4.y-dr1)));
        float df2 = 0.25f*((fabsf(c4.z-c4.y)+fabsf(c4.z-c4.w))+(fabsf(c4.z-ur2)+fabsf(c4.z-dr2)));
        float df3 = 0.25f*((fabsf(c4.w-c4.z)+fabsf(c4.w-rr3))+(fabsf(c4.w-ur3)+fabsf(c4.w-dr3)));
        ((float4*)drow)[p4] = make_float4(to_tf32(df0), to_tf32(df1), to_tf32(df2), to_tf32(df3));
    }
    red[tid] = gsum;
    __syncthreads();
    for (int k = 256; k > 0; k >>= 1) {
        if (tid < k) red[tid] += red[tid + k];
        __syncthreads();
    }
    if (tid == 0) g_gap[b][c] = red[0] * (1.0f / NL);
}

// ---------------- v reduction + silu: 512 blocks x 256 thr, 4-way channel split ----------------
__global__ __launch_bounds__(256) void k_vred(const float* __restrict__ x,
                                              const float* __restrict__ b1) {
    __shared__ float4 P0[4][64], P1[4][64], P2[4][64];
    __shared__ float s0f[VT+1], s1f[VT], s2f[VT+1];
    __shared__ float cks[3*NC], us[NMID], b1s[NMID];
    __shared__ float hLs[4], hRs[4];
    const int tid = threadIdx.x;
    const int b = blockIdx.x >> 6;
    const int tb = (blockIdx.x & 63) << 8;
    const int q = tid & 63, part = tid >> 6;
    const float* xb = x + (size_t)b * NC * NL;

    for (int t = tid; t < 3*NC; t += 256) cks[t] = (&g_ck[b][0][0])[t];
    if (tid < NMID) { us[tid] = g_u[b][tid]; b1s[tid] = b1[tid]; }
    __syncthreads();

    const int cb = part << 5;
    const float* base = xb + (size_t)cb * NL + tb;
    const bool hL = (q == 0)  && (tb > 0);
    const bool hR = (q == 63) && (tb + VT < NL);
    float a0x=0,a0y=0,a0z=0,a0w=0, a1x=0,a1y=0,a1z=0,a1w=0, a2x=0,a2y=0,a2z=0,a2w=0;
    float h = 0.f;
    #pragma unroll 8
    for (int c = 0; c < 32; c++) {
        float4 xv = ((const float4*)(base + (size_t)c * NL))[q];
        float k0 = cks[cb + c], k1 = cks[NC + cb + c], k2 = cks[2*NC + cb + c];
        a0x = fmaf(k0, xv.x, a0x); a0y = fmaf(k0, xv.y, a0y);
        a0z = fmaf(k0, xv.z, a0z); a0w = fmaf(k0, xv.w, a0w);
        a1x = fmaf(k1, xv.x, a1x); a1y = fmaf(k1, xv.y, a1y);
        a1z = fmaf(k1, xv.z, a1z); a1w = fmaf(k1, xv.w, a1w);
        a2x = fmaf(k2, xv.x, a2x); a2y = fmaf(k2, xv.y, a2y);
        a2z = fmaf(k2, xv.z, a2z); a2w = fmaf(k2, xv.w, a2w);
        if (hL) h = fmaf(k0, base[(size_t)c*NL - 1], h);
        if (hR) h = fmaf(k2, base[(size_t)c*NL + VT], h);
    }
    P0[part][q] = make_float4(a0x, a0y, a0z, a0w);
    P1[part][q] = make_float4(a1x, a1y, a1z, a1w);
    P2[part][q] = make_float4(a2x, a2y, a2z, a2w);
    if (q == 0)  hLs[part] = hL ? h : 0.f;
    if (q == 63) hRs[part] = hR ? h : 0.f;
    __syncthreads();
    if (tid < 64) {
        float4 t0 = P0[0][tid], t1 = P0[1][tid], t2 = P0[2][tid], t3 = P0[3][tid];
        float4 u0 = P1[0][tid], u1 = P1[1][tid], u2 = P1[2][tid], u3 = P1[3][tid];
        float4 w0 = P2[0][tid], w1 = P2[1][tid], w2 = P2[2][tid], w3 = P2[3][tid];
        int i0 = tid << 2;
        s0f[i0+1] = (t0.x+t1.x)+(t2.x+t3.x); s0f[i0+2] = (t0.y+t1.y)+(t2.y+t3.y);
        s0f[i0+3] = (t0.z+t1.z)+(t2.z+t3.z); s0f[i0+4] = (t0.w+t1.w)+(t2.w+t3.w);
        s1f[i0]   = (u0.x+u1.x)+(u2.x+u3.x); s1f[i0+1] = (u0.y+u1.y)+(u2.y+u3.y);
        s1f[i0+2] = (u0.z+u1.z)+(u2.z+u3.z); s1f[i0+3] = (u0.w+u1.w)+(u2.w+u3.w);
        s2f[i0]   = (w0.x+w1.x)+(w2.x+w3.x); s2f[i0+1] = (w0.y+w1.y)+(w2.y+w3.y);
        s2f[i0+2] = (w0.z+w1.z)+(w2.z+w3.z); s2f[i0+3] = (w0.w+w1.w)+(w2.w+w3.w);
        if (tid == 0)  s0f[0]  = (hLs[0]+hLs[1])+(hLs[2]+hLs[3]);
        if (tid == 63) s2f[VT] = (hRs[0]+hRs[1])+(hRs[2]+hRs[3]);
    }
    __syncthreads();
    {
        int i0 = q << 2;
        float v0 = s0f[i0]   + s1f[i0]   + s2f[i0+1];
        float v1 = s0f[i0+1] + s1f[i0+1] + s2f[i0+2];
        float v2 = s0f[i0+2] + s1f[i0+2] + s2f[i0+3];
        float v3 = s0f[i0+3] + s1f[i0+3] + s2f[i0+4];
        float* dst = g_Fg + (size_t)b*NFROWS*NL + (size_t)(2*NC)*NL + tb + i0;
        const int m0 = part << 3;
        #pragma unroll 4
        for (int m = m0; m < m0 + 8; m++) {
            float um = us[m], bm = b1s[m];
            float z0 = fmaf(um, v0, bm), z1 = fmaf(um, v1, bm);
            float z2 = fmaf(um, v2, bm), z3 = fmaf(um, v3, bm);
            *(float4*)(dst + (size_t)m * NL) = make_float4(
                to_tf32(z0 / (1.f + __expf(-z0))), to_tf32(z1 / (1.f + __expf(-z1))),
                to_tf32(z2 / (1.f + __expf(-z2))), to_tf32(z3 / (1.f + __expf(-z3))));
        }
    }
}

// ---------------- streaming GEMM with fragment-order A, writes pre-BN to out ----------------
#define GSMEM (3*8192*4)

__global__ __launch_bounds__(256, 2) void k_gemm(const float* __restrict__ x,
                                                 float* __restrict__ out) {
    extern __shared__ __align__(16) float sm[];
    const int tid = threadIdx.x;
    const int b = blockIdx.x >> 7;
    const int posb = (blockIdx.x & 127) << 7;
    const float* xb  = x + (size_t)b * NC * NL + posb;
    const float* fgb = g_Fg + (size_t)b * NFROWS * NL + posb;

    auto issueP = [&](int p, int st) {
        int k0 = p * 32;
        const float* bsrc = (k0 < NC) ? (xb + (size_t)k0 * NL) : (fgb + (size_t)(k0 - NC) * NL);
        const float* asrc = g_Bt2 + p * 4096;
        uint32_t ab = smem_u32(sm + st * 8192);
        uint32_t bb = ab + 16384;
        #pragma unroll
        for (int r = 0; r < 4; r++) {
            int f = tid + (r << 8);
            cp16(ab + f*16, asrc + f*4, true);
            int kr = f >> 5, j4 = f & 31;
            int sw = (kr*32 + (j4 ^ ((kr & 3) << 1))) * 16;
            cp16(bb + sw, bsrc + (size_t)kr*NL + (j4 << 2), true);
        }
        cp_commit();
    };
    issueP(0, 0); issueP(1, 1);

    const int lane = tid & 31, g = lane >> 2, tg = lane & 3;
    const int w = tid >> 5, m2 = w >> 2, mbase = m2 * 64, nbase = (w & 3) * 32;
    const int swa = tg << 3;
    float dacc[4][4][4];
    #pragma unroll
    for (int mt = 0; mt < 4; mt++)
        #pragma unroll
        for (int nt = 0; nt < 4; nt++)
            #pragma unroll
            for (int qq = 0; qq < 4; qq++) dacc[mt][nt][qq] = 0.f;

    auto mmaPanel = [&](const float* As, bool cvt) {
        const uint32_t* Fu = (const uint32_t*)As + 4096;
        #pragma unroll
        for (int ks = 0; ks < 4; ks++) {
            const int kr = ks * 8;
            float4 afv[4];
            #pragma unroll
            for (int mt = 0; mt < 4; mt++)
                afv[mt] = *(const float4*)(As + (((mt*8 + ks*2 + m2)*32 + lane) << 2));
            uint32_t bf[4][2];
            #pragma unroll
            for (int nt = 0; nt < 4; nt++) {
                int n = nbase + nt*8 + g;
                uint32_t v0 = Fu[(kr + tg)*128 + (n ^ swa)];
                uint32_t v1 = Fu[(kr + tg + 4)*128 + (n ^ swa)];
                bf[nt][0] = cvt ? cvt_rna_u(v0) : v0;
                bf[nt][1] = cvt ? cvt_rna_u(v1) : v1;
            }
            #pragma unroll
            for (int mt = 0; mt < 4; mt++) {
                uint32_t af[4] = { __float_as_uint(afv[mt].x), __float_as_uint(afv[mt].y),
                                   __float_as_uint(afv[mt].z), __float_as_uint(afv[mt].w) };
                #pragma unroll
                for (int nt = 0; nt < 4; nt++)
                    mma_tf32(dacc[mt][nt], af, bf[nt]);
            }
        }
    };

    int st = 0;
    #pragma unroll 1
    for (int p = 0; p < NPAN; p++) {
        if (p < NPAN-1) { CP_WAIT(1); } else { CP_WAIT(0); }
        __syncthreads();
        if (p + 2 < NPAN) issueP(p + 2, (p + 2) % 3);
        mmaPanel(sm + st * 8192, p < 4);
        st = (st == 2) ? 0 : st + 1;
    }
    __syncthreads();

    // ---- epilogue: bias, pre-BN store to out, BN partials ----
    float* sred = sm;
    #pragma unroll
    for (int mt = 0; mt < 4; mt++) {
        int o0 = mbase + mt*16 + g, o1 = o0 + 8;
        float bb0 = g_b2p[o0], bb1 = g_b2p[o1];
        float* row0 = &out[(size_t)(b*NC + o0) * NL + posb];
        float* row1 = &out[(size_t)(b*NC + o1) * NL + posb];
        float s0 = 0.f, q0 = 0.f, s1 = 0.f, q1 = 0.f;
        #pragma unroll
        for (int nt = 0; nt < 4; nt++) {
            float v0 = dacc[mt][nt][0] + bb0, v1 = dacc[mt][nt][1] + bb0;
            float v2 = dacc[mt][nt][2] + bb1, v3 = dacc[mt][nt][3] + bb1;
            int j = nbase + nt*8 + 2*tg;
            *(float2*)(row0 + j) = make_float2(v0, v1);
            *(float2*)(row1 + j) = make_float2(v2, v3);
            s0 += v0 + v1; q0 = fmaf(v0, v0, q0); q0 = fmaf(v1, v1, q0);
            s1 += v2 + v3; q1 = fmaf(v2, v2, q1); q1 = fmaf(v3, v3, q1);
        }
        s0 += __shfl_xor_sync(0xffffffff, s0, 1); s0 += __shfl_xor_sync(0xffffffff, s0, 2);
        q0 += __shfl_xor_sync(0xffffffff, q0, 1); q0 += __shfl_xor_sync(0xffffffff, q0, 2);
        s1 += __shfl_xor_sync(0xffffffff, s1, 1); s1 += __shfl_xor_sync(0xffffffff, s1, 2);
        q1 += __shfl_xor_sync(0xffffffff, q1, 1); q1 += __shfl_xor_sync(0xffffffff, q1, 2);
        if (tg == 0) {
            int nwq = w & 3;
            sred[o0*4 + nwq] = s0; sred[512 + o0*4 + nwq] = q0;
            sred[o1*4 + nwq] = s1; sred[512 + o1*4 + nwq] = q1;
        }
    }
    __syncthreads();
    if (tid < NC) {
        float s = 0.f, q = 0.f;
        #pragma unroll
        for (int t = 0; t < 4; t++) { s += sred[tid*4 + t]; q += sred[512 + tid*4 + t]; }
        g_psum[tid*NROWBLK + blockIdx.x] = s;
        g_psq [tid*NROWBLK + blockIdx.x] = q;
    }
}

// ---------------- BN stats ----------------
__global__ void k_bnstat(const float* __restrict__ gamma, const float* __restrict__ beta) {
    int c = blockIdx.x, tid = threadIdx.x;
    __shared__ float s1[256], s2[256];
    float a = 0.f, q = 0.f;
    for (int t = tid; t < NROWBLK; t += 256) { a += g_psum[c*NROWBLK + t]; q += g_psq[c*NROWBLK + t]; }
    s1[tid] = a; s2[tid] = q; __syncthreads();
    for (int s = 128; s > 0; s >>= 1) {
        if (tid < s) { s1[tid] += s1[tid+s]; s2[tid] += s2[tid+s]; }
        __syncthreads();
    }
    if (tid == 0) {
        const float invN = 1.0f / (float)(NB * NL);
        float mu  = s1[0] * invN;
        float var = s2[0] * invN - mu * mu;
        float rs  = rsqrtf(var + 1e-5f);
        float sc  = gamma[c] * rs;
        g_scale[c] = sc;
        g_shift[c] = beta[c] - mu * sc;
    }
}

// ---------------- normalize in place ----------------
__global__ __launch_bounds__(512) void k_norm(float* __restrict__ out) {
    int base = blockIdx.x * 1024 + threadIdx.x;
    #pragma unroll
    for (int r = 0; r < 2; r++) {
        int idx = base + (r << 9);
        float4 v = ((float4*)out)[idx];
        int c = (idx >> 12) & 127;
        float sc = g_scale[c], sh = g_shift[c];
        v.x = fmaf(v.x, sc, sh); v.y = fmaf(v.y, sc, sh);
        v.z = fmaf(v.z, sc, sh); v.w = fmaf(v.w, sc, sh);
        ((float4*)out)[idx] = v;
    }
}

// ---------------- launcher ----------------
extern "C" void kernel_launch(void* const* d_in, const int* in_sizes, int n_in,
                              void* d_out, int out_size) {
    const float* x            = (const float*)d_in[0];
    const float* w_spatial_in = (const float*)d_in[1];
    const float* w_dw_spatial = (const float*)d_in[2];
    const float* w_spatial_out= (const float*)d_in[3];
    const float* w_ch_in      = (const float*)d_in[4];
    const float* w_ch_dw      = (const float*)d_in[5];
    const float* w_ch_out     = (const float*)d_in[6];
    const float* w_mlp1       = (const float*)d_in[7];
    const float* b_mlp1       = (const float*)d_in[8];
    const float* w_mlp2       = (const float*)d_in[9];
    const float* b_mlp2       = (const float*)d_in[10];
    const float* diff_weight  = (const float*)d_in[11];
    const float* bn_gamma     = (const float*)d_in[12];
    const float* bn_beta      = (const float*)d_in[13];
    const float* w_out_proj   = (const float*)d_in[14];
    float* out = (float*)d_out;

    cudaFuncSetAttribute(k_gemm, cudaFuncAttributeMaxDynamicSharedMemorySize, GSMEM);

    k_prepw<<<NC, 512>>>(w_out_proj, w_spatial_out, w_dw_spatial, w_spatial_in,
                         w_mlp2, b_mlp2, diff_weight);
    k_build<<<NB*NC, 512>>>(x);     // also produces g_gap
    k_prep3<<<NB, 1024>>>(w_ch_in, w_ch_dw, w_ch_out, w_mlp1);
    k_vred <<<NB*64, 256>>>(x, b_mlp1);
    k_gemm <<<NROWBLK, 256, GSMEM>>>(x, out);
    k_bnstat<<<NC, 256>>>(bn_gamma, bn_beta);
    k_norm <<<NTOT/4/1024, 512>>>(out);
}